// round 2
// baseline (speedup 1.0000x reference)
#include <cuda_runtime.h>
#include <math.h>

#define NFEAT 256
#define NHID  128
#define NCLASS 16
#define MAXN 100000
#define MAXE 3200000

// ---------------- device scratch (static allocation, allowed) ----------------
__device__ float g_H0[(size_t)MAXN * NHID];   // x @ W1
__device__ float g_H2[(size_t)MAXN * NCLASS]; // spmm1 -> relu -> @W2 (fused)
__device__ float g_W2t[NCLASS * NHID];        // W2 transposed [16][128]
__device__ int   g_offs[MAXN + 1];
__device__ int   g_cursor[MAXN];
__device__ int   g_esrc[MAXE];
__device__ float g_ews[MAXE];

// ---------------- helpers ----------------
__device__ __forceinline__ void ffma2(float2& d, float2 a, float2 b) {
    unsigned long long& ud = reinterpret_cast<unsigned long long&>(d);
    unsigned long long  ua = reinterpret_cast<unsigned long long&>(a);
    unsigned long long  ub = reinterpret_cast<unsigned long long&>(b);
    asm("fma.rn.f32x2 %0, %1, %2, %0;" : "+l"(ud) : "l"(ua), "l"(ub));
}

__device__ __forceinline__ int block_incl_scan(int v, int* swarp, int nwarps) {
    int lane = threadIdx.x & 31, wid = threadIdx.x >> 5;
    #pragma unroll
    for (int o = 1; o < 32; o <<= 1) {
        int n = __shfl_up_sync(0xffffffffu, v, o);
        if (lane >= o) v += n;
    }
    if (lane == 31) swarp[wid] = v;
    __syncthreads();
    if (wid == 0) {
        int s = (lane < nwarps) ? swarp[lane] : 0;
        #pragma unroll
        for (int o = 1; o < 32; o <<= 1) {
            int n = __shfl_up_sync(0xffffffffu, s, o);
            if (lane >= o) s += n;
        }
        swarp[lane] = s;
    }
    __syncthreads();
    if (wid > 0) v += swarp[wid - 1];
    return v;
}

// ---------------- CSR construction ----------------
__global__ void zero_offs_kernel(int L) {
    int i = blockIdx.x * blockDim.x + threadIdx.x;
    if (i < L) g_offs[i] = 0;
}

__global__ void degree_kernel(const int* __restrict__ dst, int E) {
    int e = blockIdx.x * blockDim.x + threadIdx.x;
    if (e < E) atomicAdd(&g_offs[dst[e] + 1], 1);
}

// Single-block scan over g_offs[0..L) + W2 transpose (independent side job).
// Launch with 1024 threads, 1 block.
__global__ void scan_w2t_kernel(const float* __restrict__ W2, int L) {
    // transpose W2 [128,16] -> g_W2t [16][128]
    for (int i = threadIdx.x; i < NHID * NCLASS; i += blockDim.x) {
        int k = i >> 4, c = i & 15;
        g_W2t[c * NHID + k] = W2[i];
    }
    __shared__ int sw[32];
    __shared__ int s_carry;
    if (threadIdx.x == 0) s_carry = 0;
    __syncthreads();
    for (int base = 0; base < L; base += blockDim.x) {
        int i = base + threadIdx.x;
        int v = (i < L) ? g_offs[i] : 0;
        int carry = s_carry;                       // helper's syncs order this read
        int incl = block_incl_scan(v, sw, blockDim.x >> 5) + carry;
        if (i < L) {
            g_offs[i] = incl;
            if (i < L - 1) g_cursor[i] = incl;     // row-start cursors for fill
        }
        __syncthreads();
        if (threadIdx.x == blockDim.x - 1) s_carry = incl;
        __syncthreads();
    }
}

__global__ void fill_csr(const int* __restrict__ src, const int* __restrict__ dst,
                         const float* __restrict__ w, int E) {
    int e = blockIdx.x * blockDim.x + threadIdx.x;
    if (e >= E) return;
    int d = dst[e];
    int p = atomicAdd(&g_cursor[d], 1);
    g_esrc[p] = src[e];
    g_ews[p]  = w[e];
}

// ---------------- GEMM1: H0 = x @ W1  (N x 256 x 128, fp32 via f32x2 FMA) ----------------
__global__ void gemm1_kernel(const float* __restrict__ X, const float* __restrict__ W, int N) {
    __shared__ float As[16][128];  // x tile, transposed: As[k][row]
    __shared__ float Bs[16][128];  // W tile: Bs[k][col]
    const int tid = threadIdx.x;
    const int tx = tid & 15;   // col group -> cols [tx*8, tx*8+8)
    const int ty = tid >> 4;   // row group -> rows [ty*8, ty*8+8)
    const int bRow = blockIdx.x * 128;

    float2 acc[8][4];
    #pragma unroll
    for (int r = 0; r < 8; r++)
        #pragma unroll
        for (int c = 0; c < 4; c++) acc[r][c] = make_float2(0.f, 0.f);

    for (int kt = 0; kt < NFEAT; kt += 16) {
        #pragma unroll
        for (int i = 0; i < 2; i++) {
            int idx = tid + i * 256;                // [0,512)
            int ar = idx >> 2, akq = idx & 3;       // A: 128 rows x 4 k-quads
            float4 av = make_float4(0.f, 0.f, 0.f, 0.f);
            int grow = bRow + ar;
            if (grow < N)
                av = *reinterpret_cast<const float4*>(&X[(size_t)grow * NFEAT + kt + akq * 4]);
            As[akq * 4 + 0][ar] = av.x;
            As[akq * 4 + 1][ar] = av.y;
            As[akq * 4 + 2][ar] = av.z;
            As[akq * 4 + 3][ar] = av.w;
            int bk = idx >> 5, bc = (idx & 31) << 2; // B: 16 k-rows x 32 col-quads
            *reinterpret_cast<float4*>(&Bs[bk][bc]) =
                *reinterpret_cast<const float4*>(&W[(size_t)(kt + bk) * NHID + bc]);
        }
        __syncthreads();
        #pragma unroll
        for (int k = 0; k < 16; k++) {
            float a[8];
            *reinterpret_cast<float4*>(&a[0]) = *reinterpret_cast<const float4*>(&As[k][ty * 8]);
            *reinterpret_cast<float4*>(&a[4]) = *reinterpret_cast<const float4*>(&As[k][ty * 8 + 4]);
            float2 b[4];
            *reinterpret_cast<float4*>(&b[0]) = *reinterpret_cast<const float4*>(&Bs[k][tx * 8]);
            *reinterpret_cast<float4*>(&b[2]) = *reinterpret_cast<const float4*>(&Bs[k][tx * 8 + 4]);
            #pragma unroll
            for (int r = 0; r < 8; r++) {
                float2 ad = make_float2(a[r], a[r]);
                #pragma unroll
                for (int c = 0; c < 4; c++) ffma2(acc[r][c], ad, b[c]);
            }
        }
        __syncthreads();
    }
    #pragma unroll
    for (int r = 0; r < 8; r++) {
        int grow = bRow + ty * 8 + r;
        if (grow < N) {
            float4 o0 = make_float4(acc[r][0].x, acc[r][0].y, acc[r][1].x, acc[r][1].y);
            float4 o1 = make_float4(acc[r][2].x, acc[r][2].y, acc[r][3].x, acc[r][3].y);
            float* outp = &g_H0[(size_t)grow * NHID + tx * 8];
            *reinterpret_cast<float4*>(outp)     = o0;
            *reinterpret_cast<float4*>(outp + 4) = o1;
        }
    }
}

// ---------------- Fused SPMM1 + bias + relu + GEMM2 ----------------
// warp per dst row; lane holds float4 (4 of 128 cols) of h = relu(A@H0 + b1);
// then directly computes h @ W2 (16 classes) via L1-resident g_W2t and a
// split-butterfly warp reduction. H1 never touches memory.
__global__ void spmm1_gemm2_kernel(const float* __restrict__ b1, int N) {
    int warp = (blockIdx.x * blockDim.x + threadIdx.x) >> 5;
    int lane = threadIdx.x & 31;
    if (warp >= N) return;
    int beg = g_offs[warp], end = g_offs[warp + 1];
    const float4* H04 = reinterpret_cast<const float4*>(g_H0);
    float4 acc = make_float4(0.f, 0.f, 0.f, 0.f);
    int e = beg;
    for (; e + 1 < end; e += 2) {
        int   s0 = g_esrc[e],   s1 = g_esrc[e + 1];
        float w0 = g_ews[e],    w1 = g_ews[e + 1];
        float4 v0 = H04[(size_t)s0 * 32 + lane];
        float4 v1 = H04[(size_t)s1 * 32 + lane];
        acc.x = fmaf(w0, v0.x, acc.x); acc.y = fmaf(w0, v0.y, acc.y);
        acc.z = fmaf(w0, v0.z, acc.z); acc.w = fmaf(w0, v0.w, acc.w);
        acc.x = fmaf(w1, v1.x, acc.x); acc.y = fmaf(w1, v1.y, acc.y);
        acc.z = fmaf(w1, v1.z, acc.z); acc.w = fmaf(w1, v1.w, acc.w);
    }
    if (e < end) {
        int s0 = g_esrc[e]; float w0 = g_ews[e];
        float4 v0 = H04[(size_t)s0 * 32 + lane];
        acc.x = fmaf(w0, v0.x, acc.x); acc.y = fmaf(w0, v0.y, acc.y);
        acc.z = fmaf(w0, v0.z, acc.z); acc.w = fmaf(w0, v0.w, acc.w);
    }
    float4 bb = __ldg(&reinterpret_cast<const float4*>(b1)[lane]);
    float4 h;
    h.x = fmaxf(acc.x + bb.x, 0.f);
    h.y = fmaxf(acc.y + bb.y, 0.f);
    h.z = fmaxf(acc.z + bb.z, 0.f);
    h.w = fmaxf(acc.w + bb.w, 0.f);

    // per-lane class partials: p[c] = dot(h, W2t[c][4*lane .. 4*lane+3])
    const float4* W2t4 = reinterpret_cast<const float4*>(g_W2t);
    float p[16];
    #pragma unroll
    for (int c = 0; c < 16; c++) {
        float4 wv = __ldg(&W2t4[c * 32 + lane]);   // 8KB, L1-resident
        float t = h.x * wv.x;
        t = fmaf(h.y, wv.y, t);
        t = fmaf(h.z, wv.z, t);
        t = fmaf(h.w, wv.w, t);
        p[c] = t;
    }
    // split-butterfly reduce: 16 values over 32 lanes -> 1 value/lane
    {   // round xor=1: keep 8
        bool hi = (lane & 1);
        #pragma unroll
        for (int k = 0; k < 8; k++) {
            float send = hi ? p[k] : p[k + 8];
            float recv = __shfl_xor_sync(0xffffffffu, send, 1);
            p[k] = (hi ? p[k + 8] : p[k]) + recv;
        }
    }
    {   // round xor=2: keep 4
        bool hi = (lane & 2);
        #pragma unroll
        for (int k = 0; k < 4; k++) {
            float send = hi ? p[k] : p[k + 4];
            float recv = __shfl_xor_sync(0xffffffffu, send, 2);
            p[k] = (hi ? p[k + 4] : p[k]) + recv;
        }
    }
    {   // round xor=4: keep 2
        bool hi = (lane & 4);
        #pragma unroll
        for (int k = 0; k < 2; k++) {
            float send = hi ? p[k] : p[k + 2];
            float recv = __shfl_xor_sync(0xffffffffu, send, 4);
            p[k] = (hi ? p[k + 2] : p[k]) + recv;
        }
    }
    {   // round xor=8: keep 1
        bool hi = (lane & 8);
        float send = hi ? p[0] : p[1];
        float recv = __shfl_xor_sync(0xffffffffu, send, 8);
        p[0] = (hi ? p[1] : p[0]) + recv;
    }
    p[0] += __shfl_xor_sync(0xffffffffu, p[0], 16);
    // lane -> class (bit-reversed low 4 bits)
    int c = ((lane & 1) << 3) | ((lane & 2) << 1) | ((lane & 4) >> 1) | ((lane & 8) >> 3);
    if (lane < 16) g_H2[(size_t)warp * NCLASS + c] = p[0];
}

// ---------------- SPMM2 + bias + log_softmax, fused ----------------
// half-warp per dst row: lanes l=0..15 hold the 16 classes.
__global__ void spmm2_kernel(const float* __restrict__ b2, float* __restrict__ out, int N) {
    int gwarp = (blockIdx.x * blockDim.x + threadIdx.x) >> 5;
    int lane = threadIdx.x & 31;
    int half = lane >> 4, l = lane & 15;
    int row = gwarp * 2 + half;
    float acc = 0.f;
    if (row < N) {
        int beg = g_offs[row], end = g_offs[row + 1];
        for (int e = beg; e < end; e++) {
            int s = g_esrc[e]; float w = g_ews[e];
            acc = fmaf(w, __ldg(&g_H2[(size_t)s * NCLASS + l]), acc);
        }
    }
    acc += b2[l];
    float m = acc;
    #pragma unroll
    for (int o = 8; o > 0; o >>= 1) m = fmaxf(m, __shfl_xor_sync(0xffffffffu, m, o, 16));
    float ex = expf(acc - m);
    float s = ex;
    #pragma unroll
    for (int o = 8; o > 0; o >>= 1) s += __shfl_xor_sync(0xffffffffu, s, o, 16);
    if (row < N) out[(size_t)row * NCLASS + l] = acc - m - logf(s);
}

// ---------------- launch ----------------
extern "C" void kernel_launch(void* const* d_in, const int* in_sizes, int n_in,
                              void* d_out, int out_size) {
    const float* x   = (const float*)d_in[0];
    const float* W1  = (const float*)d_in[1];
    const float* b1  = (const float*)d_in[2];
    const float* W2  = (const float*)d_in[3];
    const float* b2  = (const float*)d_in[4];
    const float* ew  = (const float*)d_in[5];
    const int*   src = (const int*)d_in[6];
    const int*   dst = (const int*)d_in[7];
    float* out = (float*)d_out;

    const int N = in_sizes[0] / NFEAT;
    const int E = in_sizes[5];
    const int L = N + 1;

    // CSR build (by dst); launch #6 is the fused SPMM (gets the ncu slot)
    zero_offs_kernel<<<(L + 255) / 256, 256>>>(L);             // 1
    degree_kernel<<<(E + 255) / 256, 256>>>(dst, E);           // 2
    scan_w2t_kernel<<<1, 1024>>>(W2, L);                       // 3
    fill_csr<<<(E + 255) / 256, 256>>>(src, dst, ew, E);       // 4
    gemm1_kernel<<<(N + 127) / 128, 256>>>(x, W1, N);          // 5
    spmm1_gemm2_kernel<<<(N + 7) / 8, 256>>>(b1, N);           // 6  <- profiled
    spmm2_kernel<<<(N + 15) / 16, 256>>>(b2, out, N);          // 7
}

// round 3
// speedup vs baseline: 1.1505x; 1.1505x over previous
#include <cuda_runtime.h>
#include <math.h>

#define NFEAT 256
#define NHID  128
#define NCLASS 16
#define MAXN 100000
#define MAXE 3200000

// ---------------- device scratch (static allocation, allowed) ----------------
__device__ float g_H0[(size_t)MAXN * NHID];   // x @ W1
__device__ float g_H2[(size_t)MAXN * NCLASS]; // spmm1 -> relu -> @W2 (fused)
__device__ float g_W2t[NCLASS * NHID];        // W2 transposed [16][128]
__device__ int   g_offs[MAXN + 1];
__device__ int   g_cursor[MAXN];
__device__ int2  g_epair[MAXE];               // (src, weight-bits) per edge, CSR order
__device__ int   g_bsum[512];
__device__ int   g_bexc[512];

// ---------------- helpers ----------------
__device__ __forceinline__ void ffma2(float2& d, float2 a, float2 b) {
    unsigned long long& ud = reinterpret_cast<unsigned long long&>(d);
    unsigned long long  ua = reinterpret_cast<unsigned long long&>(a);
    unsigned long long  ub = reinterpret_cast<unsigned long long&>(b);
    asm("fma.rn.f32x2 %0, %1, %2, %0;" : "+l"(ud) : "l"(ua), "l"(ub));
}

__device__ __forceinline__ int block_incl_scan(int v, int* swarp, int nwarps) {
    int lane = threadIdx.x & 31, wid = threadIdx.x >> 5;
    #pragma unroll
    for (int o = 1; o < 32; o <<= 1) {
        int n = __shfl_up_sync(0xffffffffu, v, o);
        if (lane >= o) v += n;
    }
    if (lane == 31) swarp[wid] = v;
    __syncthreads();
    if (wid == 0) {
        int s = (lane < nwarps) ? swarp[lane] : 0;
        #pragma unroll
        for (int o = 1; o < 32; o <<= 1) {
            int n = __shfl_up_sync(0xffffffffu, s, o);
            if (lane >= o) s += n;
        }
        swarp[lane] = s;
    }
    __syncthreads();
    if (wid > 0) v += swarp[wid - 1];
    return v;
}

// ---------------- CSR construction ----------------
// zero offsets; block 0 also transposes W2 (independent side job)
__global__ void zero_w2t_kernel(const float* __restrict__ W2, int L) {
    if (blockIdx.x == gridDim.x - 1) {
        for (int i = threadIdx.x; i < NHID * NCLASS; i += blockDim.x) {
            int k = i >> 4, c = i & 15;
            g_W2t[c * NHID + k] = W2[i];
        }
    }
    int i = blockIdx.x * blockDim.x + threadIdx.x;
    if (i < L) g_offs[i] = 0;
}

__global__ void degree_kernel(const int* __restrict__ dst, int E) {
    int e = blockIdx.x * blockDim.x + threadIdx.x;
    if (e < E) atomicAdd(&g_offs[dst[e] + 1], 1);
}

__global__ void scan_block_sums(int L) {
    __shared__ int sw[32];
    int i = blockIdx.x * blockDim.x + threadIdx.x;
    int v = (i < L) ? g_offs[i] : 0;
    int incl = block_incl_scan(v, sw, blockDim.x >> 5);
    if (threadIdx.x == blockDim.x - 1) g_bsum[blockIdx.x] = incl;
}

__global__ void scan_partials(int NB) {
    __shared__ int sw[32];
    int t = threadIdx.x;
    int v = (t < NB) ? g_bsum[t] : 0;
    int incl = block_incl_scan(v, sw, blockDim.x >> 5);
    g_bexc[t] = incl - v;  // exclusive prefix of block sums
}

__global__ void scan_apply(int L) {
    __shared__ int sw[32];
    int i = blockIdx.x * blockDim.x + threadIdx.x;
    int v = (i < L) ? g_offs[i] : 0;
    int incl = block_incl_scan(v, sw, blockDim.x >> 5);
    if (i < L) {
        int val = incl + g_bexc[blockIdx.x];
        g_offs[i] = val;
        if (i < L - 1) g_cursor[i] = val;  // row start cursors for fill
    }
}

__global__ void fill_csr(const int* __restrict__ src, const int* __restrict__ dst,
                         const float* __restrict__ w, int E) {
    int e = blockIdx.x * blockDim.x + threadIdx.x;
    if (e >= E) return;
    int d = dst[e];
    int p = atomicAdd(&g_cursor[d], 1);
    g_epair[p] = make_int2(src[e], __float_as_int(w[e]));  // one 8B scattered store
}

// ---------------- GEMM1: H0 = x @ W1  (N x 256 x 128, fp32 via f32x2 FMA) ----------------
__global__ void gemm1_kernel(const float* __restrict__ X, const float* __restrict__ W, int N) {
    __shared__ float As[16][128];  // x tile, transposed: As[k][row]
    __shared__ float Bs[16][128];  // W tile: Bs[k][col]
    const int tid = threadIdx.x;
    const int tx = tid & 15;   // col group -> cols [tx*8, tx*8+8)
    const int ty = tid >> 4;   // row group -> rows [ty*8, ty*8+8)
    const int bRow = blockIdx.x * 128;

    float2 acc[8][4];
    #pragma unroll
    for (int r = 0; r < 8; r++)
        #pragma unroll
        for (int c = 0; c < 4; c++) acc[r][c] = make_float2(0.f, 0.f);

    for (int kt = 0; kt < NFEAT; kt += 16) {
        #pragma unroll
        for (int i = 0; i < 2; i++) {
            int idx = tid + i * 256;                // [0,512)
            int ar = idx >> 2, akq = idx & 3;       // A: 128 rows x 4 k-quads
            float4 av = make_float4(0.f, 0.f, 0.f, 0.f);
            int grow = bRow + ar;
            if (grow < N)
                av = *reinterpret_cast<const float4*>(&X[(size_t)grow * NFEAT + kt + akq * 4]);
            As[akq * 4 + 0][ar] = av.x;
            As[akq * 4 + 1][ar] = av.y;
            As[akq * 4 + 2][ar] = av.z;
            As[akq * 4 + 3][ar] = av.w;
            int bk = idx >> 5, bc = (idx & 31) << 2; // B: 16 k-rows x 32 col-quads
            *reinterpret_cast<float4*>(&Bs[bk][bc]) =
                *reinterpret_cast<const float4*>(&W[(size_t)(kt + bk) * NHID + bc]);
        }
        __syncthreads();
        #pragma unroll
        for (int k = 0; k < 16; k++) {
            float a[8];
            *reinterpret_cast<float4*>(&a[0]) = *reinterpret_cast<const float4*>(&As[k][ty * 8]);
            *reinterpret_cast<float4*>(&a[4]) = *reinterpret_cast<const float4*>(&As[k][ty * 8 + 4]);
            float2 b[4];
            *reinterpret_cast<float4*>(&b[0]) = *reinterpret_cast<const float4*>(&Bs[k][tx * 8]);
            *reinterpret_cast<float4*>(&b[2]) = *reinterpret_cast<const float4*>(&Bs[k][tx * 8 + 4]);
            #pragma unroll
            for (int r = 0; r < 8; r++) {
                float2 ad = make_float2(a[r], a[r]);
                #pragma unroll
                for (int c = 0; c < 4; c++) ffma2(acc[r][c], ad, b[c]);
            }
        }
        __syncthreads();
    }
    #pragma unroll
    for (int r = 0; r < 8; r++) {
        int grow = bRow + ty * 8 + r;
        if (grow < N) {
            float4 o0 = make_float4(acc[r][0].x, acc[r][0].y, acc[r][1].x, acc[r][1].y);
            float4 o1 = make_float4(acc[r][2].x, acc[r][2].y, acc[r][3].x, acc[r][3].y);
            float* outp = &g_H0[(size_t)grow * NHID + tx * 8];
            *reinterpret_cast<float4*>(outp)     = o0;
            *reinterpret_cast<float4*>(outp + 4) = o1;
        }
    }
}

// ---------------- Fused SPMM1 + bias + relu + GEMM2 ----------------
// warp per dst row; lane holds float4 (4 of 128 cols) of h = relu(A@H0 + b1);
// then directly computes h @ W2 (16 classes) via L1-resident g_W2t and a
// split-butterfly warp reduction. H1 never touches memory.
__global__ void spmm1_gemm2_kernel(const float* __restrict__ b1, int N) {
    int warp = (blockIdx.x * blockDim.x + threadIdx.x) >> 5;
    int lane = threadIdx.x & 31;
    if (warp >= N) return;
    int beg = g_offs[warp], end = g_offs[warp + 1];
    const float4* H04 = reinterpret_cast<const float4*>(g_H0);
    float4 acc = make_float4(0.f, 0.f, 0.f, 0.f);
    int e = beg;
    for (; e + 1 < end; e += 2) {
        int2 p0 = g_epair[e], p1 = g_epair[e + 1];
        float w0 = __int_as_float(p0.y), w1 = __int_as_float(p1.y);
        float4 v0 = H04[(size_t)p0.x * 32 + lane];
        float4 v1 = H04[(size_t)p1.x * 32 + lane];
        acc.x = fmaf(w0, v0.x, acc.x); acc.y = fmaf(w0, v0.y, acc.y);
        acc.z = fmaf(w0, v0.z, acc.z); acc.w = fmaf(w0, v0.w, acc.w);
        acc.x = fmaf(w1, v1.x, acc.x); acc.y = fmaf(w1, v1.y, acc.y);
        acc.z = fmaf(w1, v1.z, acc.z); acc.w = fmaf(w1, v1.w, acc.w);
    }
    if (e < end) {
        int2 p0 = g_epair[e];
        float w0 = __int_as_float(p0.y);
        float4 v0 = H04[(size_t)p0.x * 32 + lane];
        acc.x = fmaf(w0, v0.x, acc.x); acc.y = fmaf(w0, v0.y, acc.y);
        acc.z = fmaf(w0, v0.z, acc.z); acc.w = fmaf(w0, v0.w, acc.w);
    }
    float4 bb = __ldg(&reinterpret_cast<const float4*>(b1)[lane]);
    float4 h;
    h.x = fmaxf(acc.x + bb.x, 0.f);
    h.y = fmaxf(acc.y + bb.y, 0.f);
    h.z = fmaxf(acc.z + bb.z, 0.f);
    h.w = fmaxf(acc.w + bb.w, 0.f);

    // per-lane class partials: p[c] = dot(h, W2t[c][4*lane .. 4*lane+3])
    const float4* W2t4 = reinterpret_cast<const float4*>(g_W2t);
    float p[16];
    #pragma unroll
    for (int c = 0; c < 16; c++) {
        float4 wv = __ldg(&W2t4[c * 32 + lane]);   // 8KB, L1-resident
        float t = h.x * wv.x;
        t = fmaf(h.y, wv.y, t);
        t = fmaf(h.z, wv.z, t);
        t = fmaf(h.w, wv.w, t);
        p[c] = t;
    }
    // split-butterfly reduce: 16 values over 32 lanes -> 1 value/lane
    {   bool hi = (lane & 1);
        #pragma unroll
        for (int k = 0; k < 8; k++) {
            float send = hi ? p[k] : p[k + 8];
            float recv = __shfl_xor_sync(0xffffffffu, send, 1);
            p[k] = (hi ? p[k + 8] : p[k]) + recv;
        }
    }
    {   bool hi = (lane & 2);
        #pragma unroll
        for (int k = 0; k < 4; k++) {
            float send = hi ? p[k] : p[k + 4];
            float recv = __shfl_xor_sync(0xffffffffu, send, 2);
            p[k] = (hi ? p[k + 4] : p[k]) + recv;
        }
    }
    {   bool hi = (lane & 4);
        #pragma unroll
        for (int k = 0; k < 2; k++) {
            float send = hi ? p[k] : p[k + 2];
            float recv = __shfl_xor_sync(0xffffffffu, send, 4);
            p[k] = (hi ? p[k + 2] : p[k]) + recv;
        }
    }
    {   bool hi = (lane & 8);
        float send = hi ? p[0] : p[1];
        float recv = __shfl_xor_sync(0xffffffffu, send, 8);
        p[0] = (hi ? p[1] : p[0]) + recv;
    }
    p[0] += __shfl_xor_sync(0xffffffffu, p[0], 16);
    // lane -> class (bit-reversed low 4 bits)
    int c = ((lane & 1) << 3) | ((lane & 2) << 1) | ((lane & 4) >> 1) | ((lane & 8) >> 3);
    if (lane < 16) g_H2[(size_t)warp * NCLASS + c] = p[0];
}

// ---------------- SPMM2 + bias + log_softmax, fused ----------------
// half-warp per dst row: lanes l=0..15 hold the 16 classes.
__global__ void spmm2_kernel(const float* __restrict__ b2, float* __restrict__ out, int N) {
    int gwarp = (blockIdx.x * blockDim.x + threadIdx.x) >> 5;
    int lane = threadIdx.x & 31;
    int half = lane >> 4, l = lane & 15;
    int row = gwarp * 2 + half;
    float acc = 0.f;
    if (row < N) {
        int beg = g_offs[row], end = g_offs[row + 1];
        for (int e = beg; e < end; e++) {
            int2 pe = g_epair[e];
            float w = __int_as_float(pe.y);
            acc = fmaf(w, __ldg(&g_H2[(size_t)pe.x * NCLASS + l]), acc);
        }
    }
    acc += b2[l];
    float m = acc;
    #pragma unroll
    for (int o = 8; o > 0; o >>= 1) m = fmaxf(m, __shfl_xor_sync(0xffffffffu, m, o, 16));
    float ex = expf(acc - m);
    float s = ex;
    #pragma unroll
    for (int o = 8; o > 0; o >>= 1) s += __shfl_xor_sync(0xffffffffu, s, o, 16);
    if (row < N) out[(size_t)row * NCLASS + l] = acc - m - logf(s);
}

// ---------------- launch ----------------
extern "C" void kernel_launch(void* const* d_in, const int* in_sizes, int n_in,
                              void* d_out, int out_size) {
    const float* x   = (const float*)d_in[0];
    const float* W1  = (const float*)d_in[1];
    const float* b1  = (const float*)d_in[2];
    const float* W2  = (const float*)d_in[3];
    const float* b2  = (const float*)d_in[4];
    const float* ew  = (const float*)d_in[5];
    const int*   src = (const int*)d_in[6];
    const int*   dst = (const int*)d_in[7];
    float* out = (float*)d_out;

    const int N = in_sizes[0] / NFEAT;
    const int E = in_sizes[5];
    const int L = N + 1;
    const int NB = (L + 255) / 256;   // <= 512

    zero_w2t_kernel<<<NB, 256>>>(W2, L);                       // 1
    degree_kernel<<<(E + 255) / 256, 256>>>(dst, E);           // 2
    scan_block_sums<<<NB, 256>>>(L);                           // 3
    gemm1_kernel<<<(N + 127) / 128, 256>>>(x, W1, N);          // 4  <- profiled slot
    scan_partials<<<1, 512>>>(NB);                             // 5
    scan_apply<<<NB, 256>>>(L);                                // 6
    fill_csr<<<(E + 255) / 256, 256>>>(src, dst, ew, E);       // 7
    spmm1_gemm2_kernel<<<(N + 7) / 8, 256>>>(b1, N);           // 8
    spmm2_kernel<<<(N + 15) / 16, 256>>>(b2, out, N);          // 9
}

// round 6
// speedup vs baseline: 1.3664x; 1.1876x over previous
#include <cuda_runtime.h>
#include <cuda_bf16.h>
#include <math.h>
#include <stdint.h>

#define NFEAT 256
#define NHID  128
#define NCLASS 16
#define MAXN 100000
#define MAXE 3200000

// ---------------- device scratch (static allocation, allowed) ----------------
__device__ float g_H0[(size_t)MAXN * NHID];   // x @ W1
__device__ float g_H2[(size_t)MAXN * NCLASS]; // spmm1 -> relu -> @W2 (fused)
__device__ float g_W2t[NCLASS * NHID];        // W2 transposed [16][128]
__device__ __nv_bfloat16 g_Bhi[NHID * NFEAT]; // W1^T split-high [n][k]
__device__ __nv_bfloat16 g_Blo[NHID * NFEAT]; // W1^T split-low  [n][k]
__device__ int   g_offs[MAXN + 1];
__device__ int   g_cursor[MAXN];
__device__ int2  g_epair[MAXE];               // (src, weight-bits), CSR order
__device__ int   g_bsum[512];
__device__ int   g_bexc[512];

// ---------------- mma.sync m16n8k16 bf16 (sm_80+ baseline, sm_103-safe) -----
__device__ __forceinline__ void mma16816(float* c, const uint32_t* a, const uint32_t* b) {
    asm volatile("mma.sync.aligned.m16n8k16.row.col.f32.bf16.bf16.f32 "
                 "{%0,%1,%2,%3}, {%4,%5,%6,%7}, {%8,%9}, {%0,%1,%2,%3};"
                 : "+f"(c[0]), "+f"(c[1]), "+f"(c[2]), "+f"(c[3])
                 : "r"(a[0]), "r"(a[1]), "r"(a[2]), "r"(a[3]),
                   "r"(b[0]), "r"(b[1]));
}

// ---------------- scan helper ----------------
__device__ __forceinline__ int block_incl_scan(int v, int* swarp, int nwarps) {
    int lane = threadIdx.x & 31, wid = threadIdx.x >> 5;
    #pragma unroll
    for (int o = 1; o < 32; o <<= 1) {
        int n = __shfl_up_sync(0xffffffffu, v, o);
        if (lane >= o) v += n;
    }
    if (lane == 31) swarp[wid] = v;
    __syncthreads();
    if (wid == 0) {
        int s = (lane < nwarps) ? swarp[lane] : 0;
        #pragma unroll
        for (int o = 1; o < 32; o <<= 1) {
            int n = __shfl_up_sync(0xffffffffu, s, o);
            if (lane >= o) s += n;
        }
        swarp[lane] = s;
    }
    __syncthreads();
    if (wid > 0) v += swarp[wid - 1];
    return v;
}

// ---------------- prep: zero offs + split-transpose W1 + transpose W2 --------
__global__ void zero_prep_kernel(const float* __restrict__ W1, const float* __restrict__ W2, int L) {
    int b = blockIdx.x;
    if (b < NHID) {
        int n = b, k = threadIdx.x;      // 256 threads = 256 k
        float v = W1[(size_t)k * NHID + n];
        __nv_bfloat16 hi = __float2bfloat16(v);
        __nv_bfloat16 lo = __float2bfloat16(v - __bfloat162float(hi));
        g_Bhi[n * NFEAT + k] = hi;
        g_Blo[n * NFEAT + k] = lo;
    }
    if (b == gridDim.x - 1) {
        for (int i = threadIdx.x; i < NHID * NCLASS; i += blockDim.x) {
            int k = i >> 4, c = i & 15;
            g_W2t[c * NHID + k] = W2[i];
        }
    }
    int i = b * blockDim.x + threadIdx.x;
    if (i < L) g_offs[i] = 0;
}

// ---------------- CSR construction ----------------
__global__ void degree_kernel(const int* __restrict__ dst, int E) {
    int e = blockIdx.x * blockDim.x + threadIdx.x;
    if (e < E) atomicAdd(&g_offs[dst[e] + 1], 1);
}
__global__ void scan_block_sums(int L) {
    __shared__ int sw[32];
    int i = blockIdx.x * blockDim.x + threadIdx.x;
    int v = (i < L) ? g_offs[i] : 0;
    int incl = block_incl_scan(v, sw, blockDim.x >> 5);
    if (threadIdx.x == blockDim.x - 1) g_bsum[blockIdx.x] = incl;
}
__global__ void scan_partials(int NB) {
    __shared__ int sw[32];
    int t = threadIdx.x;
    int v = (t < NB) ? g_bsum[t] : 0;
    int incl = block_incl_scan(v, sw, blockDim.x >> 5);
    g_bexc[t] = incl - v;
}
__global__ void scan_apply(int L) {
    __shared__ int sw[32];
    int i = blockIdx.x * blockDim.x + threadIdx.x;
    int v = (i < L) ? g_offs[i] : 0;
    int incl = block_incl_scan(v, sw, blockDim.x >> 5);
    if (i < L) {
        int val = incl + g_bexc[blockIdx.x];
        g_offs[i] = val;
        if (i < L - 1) g_cursor[i] = val;
    }
}
__global__ void fill_csr(const int* __restrict__ src, const int* __restrict__ dst,
                         const float* __restrict__ w, int E) {
    int e = blockIdx.x * blockDim.x + threadIdx.x;
    if (e >= E) return;
    int d = dst[e];
    int p = atomicAdd(&g_cursor[d], 1);
    g_epair[p] = make_int2(src[e], __float_as_int(w[e]));
}

// ---------------- GEMM1: H0 = x @ W1 via bf16-split mma.sync -----------------
// 128x128 tile per CTA, 8 warps (4m x 2n), warp = 32x64 = 2x8 m16n8k16 tiles.
// K staged in 32-wide chunks. 3-term split: ah*bh + ah*bl + al*bh.
// ASTR must be a multiple of 8 bf16 (16B) for uint4 staging stores; 40 also
// gives conflict-free 32-bit fragment loads (stride 20 words covers all banks).
#define ASTR 40

__global__ void __launch_bounds__(256) gemm1_mma_kernel(const float* __restrict__ X, int N) {
    __shared__ __nv_bfloat16 sAh[128][ASTR];
    __shared__ __nv_bfloat16 sAl[128][ASTR];
    __shared__ __nv_bfloat16 sBh[128][ASTR];
    __shared__ __nv_bfloat16 sBl[128][ASTR];

    const int tid = threadIdx.x, lane = tid & 31, wid = tid >> 5;
    const int wm = wid >> 1, wn = wid & 1;          // warp grid 4x2
    const int r = lane >> 2, cc = (lane & 3) * 2;   // groupID / in-group k-pair
    const int bRow = blockIdx.x * 128;

    float acc[2][8][4];
    #pragma unroll
    for (int mt = 0; mt < 2; mt++)
        #pragma unroll
        for (int nt = 0; nt < 8; nt++)
            #pragma unroll
            for (int q = 0; q < 4; q++) acc[mt][nt][q] = 0.f;

    for (int kc = 0; kc < NFEAT; kc += 32) {
        // ---- stage A chunk: 128 rows x 32 k, f32 -> bf16 hi/lo ----
        #pragma unroll
        for (int i = 0; i < 4; i++) {
            int slot = i * 256 + tid;           // 1024 float4 slots
            int row = slot >> 3, q = slot & 7;  // 8 float4 per row
            float4 v = make_float4(0.f, 0.f, 0.f, 0.f);
            if (bRow + row < N)
                v = *reinterpret_cast<const float4*>(&X[(size_t)(bRow + row) * NFEAT + kc + q * 4]);
            __nv_bfloat16 hx = __float2bfloat16(v.x), hy = __float2bfloat16(v.y);
            __nv_bfloat16 hz = __float2bfloat16(v.z), hw = __float2bfloat16(v.w);
            sAh[row][q * 4 + 0] = hx; sAh[row][q * 4 + 1] = hy;
            sAh[row][q * 4 + 2] = hz; sAh[row][q * 4 + 3] = hw;
            sAl[row][q * 4 + 0] = __float2bfloat16(v.x - __bfloat162float(hx));
            sAl[row][q * 4 + 1] = __float2bfloat16(v.y - __bfloat162float(hy));
            sAl[row][q * 4 + 2] = __float2bfloat16(v.z - __bfloat162float(hz));
            sAl[row][q * 4 + 3] = __float2bfloat16(v.w - __bfloat162float(hw));
        }
        // ---- stage B chunk: 128 n x 32 k, pre-split bf16 (16B-aligned rows) ----
        #pragma unroll
        for (int i = 0; i < 2; i++) {
            int slot = i * 256 + tid;           // 512 uint4 slots
            int n = slot >> 2, kq = slot & 3;   // 4 x (8 bf16) per row
            uint4 vh = *reinterpret_cast<const uint4*>(&g_Bhi[n * NFEAT + kc + kq * 8]);
            uint4 vl = *reinterpret_cast<const uint4*>(&g_Blo[n * NFEAT + kc + kq * 8]);
            *reinterpret_cast<uint4*>(&sBh[n][kq * 8]) = vh;
            *reinterpret_cast<uint4*>(&sBl[n][kq * 8]) = vl;
        }
        __syncthreads();

        #pragma unroll
        for (int ks = 0; ks < 32; ks += 16) {
            uint32_t Ah[2][4], Al[2][4];
            #pragma unroll
            for (int mt = 0; mt < 2; mt++) {
                int row0 = wm * 32 + mt * 16 + r;
                Ah[mt][0] = *reinterpret_cast<const uint32_t*>(&sAh[row0][ks + cc]);
                Ah[mt][1] = *reinterpret_cast<const uint32_t*>(&sAh[row0 + 8][ks + cc]);
                Ah[mt][2] = *reinterpret_cast<const uint32_t*>(&sAh[row0][ks + cc + 8]);
                Ah[mt][3] = *reinterpret_cast<const uint32_t*>(&sAh[row0 + 8][ks + cc + 8]);
                Al[mt][0] = *reinterpret_cast<const uint32_t*>(&sAl[row0][ks + cc]);
                Al[mt][1] = *reinterpret_cast<const uint32_t*>(&sAl[row0 + 8][ks + cc]);
                Al[mt][2] = *reinterpret_cast<const uint32_t*>(&sAl[row0][ks + cc + 8]);
                Al[mt][3] = *reinterpret_cast<const uint32_t*>(&sAl[row0 + 8][ks + cc + 8]);
            }
            #pragma unroll
            for (int nt = 0; nt < 8; nt++) {
                int n0 = wn * 64 + nt * 8 + r;   // B col = groupID
                uint32_t Bh[2], Bl[2];
                Bh[0] = *reinterpret_cast<const uint32_t*>(&sBh[n0][ks + cc]);
                Bh[1] = *reinterpret_cast<const uint32_t*>(&sBh[n0][ks + cc + 8]);
                Bl[0] = *reinterpret_cast<const uint32_t*>(&sBl[n0][ks + cc]);
                Bl[1] = *reinterpret_cast<const uint32_t*>(&sBl[n0][ks + cc + 8]);
                #pragma unroll
                for (int mt = 0; mt < 2; mt++) {
                    mma16816(acc[mt][nt], Ah[mt], Bh);
                    mma16816(acc[mt][nt], Ah[mt], Bl);
                    mma16816(acc[mt][nt], Al[mt], Bh);
                }
            }
        }
        __syncthreads();
    }

    // ---- epilogue ----
    #pragma unroll
    for (int mt = 0; mt < 2; mt++) {
        int row0 = bRow + wm * 32 + mt * 16 + r;
        #pragma unroll
        for (int nt = 0; nt < 8; nt++) {
            int col = wn * 64 + nt * 8 + cc;
            if (row0 < N)
                *reinterpret_cast<float2*>(&g_H0[(size_t)row0 * NHID + col]) =
                    make_float2(acc[mt][nt][0], acc[mt][nt][1]);
            if (row0 + 8 < N)
                *reinterpret_cast<float2*>(&g_H0[(size_t)(row0 + 8) * NHID + col]) =
                    make_float2(acc[mt][nt][2], acc[mt][nt][3]);
        }
    }
}

// ---------------- Fused SPMM1 + bias + relu + GEMM2 ----------------
__global__ void spmm1_gemm2_kernel(const float* __restrict__ b1, int N) {
    int warp = (blockIdx.x * blockDim.x + threadIdx.x) >> 5;
    int lane = threadIdx.x & 31;
    if (warp >= N) return;
    int beg = g_offs[warp], end = g_offs[warp + 1];
    const float4* H04 = reinterpret_cast<const float4*>(g_H0);
    float4 acc = make_float4(0.f, 0.f, 0.f, 0.f);
    int e = beg;
    for (; e + 1 < end; e += 2) {
        int2 p0 = g_epair[e], p1 = g_epair[e + 1];
        float w0 = __int_as_float(p0.y), w1 = __int_as_float(p1.y);
        float4 v0 = H04[(size_t)p0.x * 32 + lane];
        float4 v1 = H04[(size_t)p1.x * 32 + lane];
        acc.x = fmaf(w0, v0.x, acc.x); acc.y = fmaf(w0, v0.y, acc.y);
        acc.z = fmaf(w0, v0.z, acc.z); acc.w = fmaf(w0, v0.w, acc.w);
        acc.x = fmaf(w1, v1.x, acc.x); acc.y = fmaf(w1, v1.y, acc.y);
        acc.z = fmaf(w1, v1.z, acc.z); acc.w = fmaf(w1, v1.w, acc.w);
    }
    if (e < end) {
        int2 p0 = g_epair[e];
        float w0 = __int_as_float(p0.y);
        float4 v0 = H04[(size_t)p0.x * 32 + lane];
        acc.x = fmaf(w0, v0.x, acc.x); acc.y = fmaf(w0, v0.y, acc.y);
        acc.z = fmaf(w0, v0.z, acc.z); acc.w = fmaf(w0, v0.w, acc.w);
    }
    float4 bb = __ldg(&reinterpret_cast<const float4*>(b1)[lane]);
    float4 h;
    h.x = fmaxf(acc.x + bb.x, 0.f);
    h.y = fmaxf(acc.y + bb.y, 0.f);
    h.z = fmaxf(acc.z + bb.z, 0.f);
    h.w = fmaxf(acc.w + bb.w, 0.f);

    const float4* W2t4 = reinterpret_cast<const float4*>(g_W2t);
    float p[16];
    #pragma unroll
    for (int c = 0; c < 16; c++) {
        float4 wv = __ldg(&W2t4[c * 32 + lane]);
        float t = h.x * wv.x;
        t = fmaf(h.y, wv.y, t);
        t = fmaf(h.z, wv.z, t);
        t = fmaf(h.w, wv.w, t);
        p[c] = t;
    }
    {   bool hi = (lane & 1);
        #pragma unroll
        for (int k = 0; k < 8; k++) {
            float send = hi ? p[k] : p[k + 8];
            float recv = __shfl_xor_sync(0xffffffffu, send, 1);
            p[k] = (hi ? p[k + 8] : p[k]) + recv;
        }
    }
    {   bool hi = (lane & 2);
        #pragma unroll
        for (int k = 0; k < 4; k++) {
            float send = hi ? p[k] : p[k + 4];
            float recv = __shfl_xor_sync(0xffffffffu, send, 2);
            p[k] = (hi ? p[k + 4] : p[k]) + recv;
        }
    }
    {   bool hi = (lane & 4);
        #pragma unroll
        for (int k = 0; k < 2; k++) {
            float send = hi ? p[k] : p[k + 2];
            float recv = __shfl_xor_sync(0xffffffffu, send, 4);
            p[k] = (hi ? p[k + 2] : p[k]) + recv;
        }
    }
    {   bool hi = (lane & 8);
        float send = hi ? p[0] : p[1];
        float recv = __shfl_xor_sync(0xffffffffu, send, 8);
        p[0] = (hi ? p[1] : p[0]) + recv;
    }
    p[0] += __shfl_xor_sync(0xffffffffu, p[0], 16);
    int c = ((lane & 1) << 3) | ((lane & 2) << 1) | ((lane & 4) >> 1) | ((lane & 8) >> 3);
    if (lane < 16) g_H2[(size_t)warp * NCLASS + c] = p[0];
}

// ---------------- SPMM2 + bias + log_softmax ----------------
__global__ void spmm2_kernel(const float* __restrict__ b2, float* __restrict__ out, int N) {
    int gwarp = (blockIdx.x * blockDim.x + threadIdx.x) >> 5;
    int lane = threadIdx.x & 31;
    int half = lane >> 4, l = lane & 15;
    int row = gwarp * 2 + half;
    float acc = 0.f;
    if (row < N) {
        int beg = g_offs[row], end = g_offs[row + 1];
        for (int e = beg; e < end; e++) {
            int2 pe = g_epair[e];
            float w = __int_as_float(pe.y);
            acc = fmaf(w, __ldg(&g_H2[(size_t)pe.x * NCLASS + l]), acc);
        }
    }
    acc += b2[l];
    float m = acc;
    #pragma unroll
    for (int o = 8; o > 0; o >>= 1) m = fmaxf(m, __shfl_xor_sync(0xffffffffu, m, o, 16));
    float ex = expf(acc - m);
    float s = ex;
    #pragma unroll
    for (int o = 8; o > 0; o >>= 1) s += __shfl_xor_sync(0xffffffffu, s, o, 16);
    if (row < N) out[(size_t)row * NCLASS + l] = acc - m - logf(s);
}

// ---------------- launch ----------------
extern "C" void kernel_launch(void* const* d_in, const int* in_sizes, int n_in,
                              void* d_out, int out_size) {
    const float* x   = (const float*)d_in[0];
    const float* W1  = (const float*)d_in[1];
    const float* b1  = (const float*)d_in[2];
    const float* W2  = (const float*)d_in[3];
    const float* b2  = (const float*)d_in[4];
    const float* ew  = (const float*)d_in[5];
    const int*   src = (const int*)d_in[6];
    const int*   dst = (const int*)d_in[7];
    float* out = (float*)d_out;

    const int N = in_sizes[0] / NFEAT;
    const int E = in_sizes[5];
    const int L = N + 1;
    const int NB = (L + 255) / 256;   // <= 512

    zero_prep_kernel<<<NB, 256>>>(W1, W2, L);                     // 1
    degree_kernel<<<(E + 255) / 256, 256>>>(dst, E);              // 2
    scan_block_sums<<<NB, 256>>>(L);                              // 3
    gemm1_mma_kernel<<<(N + 127) / 128, 256>>>(x, N);             // 4 <- profiled
    scan_partials<<<1, 512>>>(NB);                                // 5
    scan_apply<<<NB, 256>>>(L);                                   // 6
    fill_csr<<<(E + 255) / 256, 256>>>(src, dst, ew, E);          // 7
    spmm1_gemm2_kernel<<<(N + 7) / 8, 256>>>(b1, N);              // 8
    spmm2_kernel<<<(N + 15) / 16, 256>>>(b2, out, N);             // 9
}

// round 7
// speedup vs baseline: 1.4996x; 1.0975x over previous
#include <cuda_runtime.h>
#include <cuda_bf16.h>
#include <math.h>
#include <stdint.h>

#define NFEAT 256
#define NHID  128
#define NCLASS 16
#define MAXN 100000
#define MAXE 3200000

// ---------------- device scratch (static allocation, allowed) ----------------
__device__ float g_H0[(size_t)MAXN * NHID];   // x @ W1
__device__ float g_H2[(size_t)MAXN * NCLASS]; // spmm1 -> relu -> @W2 (fused)
__device__ float g_W2t[NCLASS * NHID];        // W2 transposed [16][128]
__device__ __nv_bfloat16 g_Bhi[NHID * NFEAT]; // W1^T split-high [n][k]
__device__ __nv_bfloat16 g_Blo[NHID * NFEAT]; // W1^T split-low  [n][k]
__device__ int   g_offs[MAXN + 1];
__device__ int   g_cursor[MAXN];
__device__ int2  g_epair[MAXE];               // (src, weight-bits), CSR order
__device__ int   g_bsum[512];
__device__ int   g_bexc[512];

// ---------------- mma.sync m16n8k16 bf16 (sm_80+ baseline, sm_103-safe) -----
__device__ __forceinline__ void mma16816(float* c, const uint32_t* a, const uint32_t* b) {
    asm volatile("mma.sync.aligned.m16n8k16.row.col.f32.bf16.bf16.f32 "
                 "{%0,%1,%2,%3}, {%4,%5,%6,%7}, {%8,%9}, {%0,%1,%2,%3};"
                 : "+f"(c[0]), "+f"(c[1]), "+f"(c[2]), "+f"(c[3])
                 : "r"(a[0]), "r"(a[1]), "r"(a[2]), "r"(a[3]),
                   "r"(b[0]), "r"(b[1]));
}

#define CP_ASYNC_16(smem_u32, gptr) \
    asm volatile("cp.async.cg.shared.global [%0], [%1], 16;" \
                 :: "r"(smem_u32), "l"(gptr) : "memory")
#define CP_ASYNC_COMMIT() asm volatile("cp.async.commit_group;" ::: "memory")
#define CP_ASYNC_WAIT0()  asm volatile("cp.async.wait_group 0;" ::: "memory")

// ---------------- scan helper ----------------
__device__ __forceinline__ int block_incl_scan(int v, int* swarp, int nwarps) {
    int lane = threadIdx.x & 31, wid = threadIdx.x >> 5;
    #pragma unroll
    for (int o = 1; o < 32; o <<= 1) {
        int n = __shfl_up_sync(0xffffffffu, v, o);
        if (lane >= o) v += n;
    }
    if (lane == 31) swarp[wid] = v;
    __syncthreads();
    if (wid == 0) {
        int s = (lane < nwarps) ? swarp[lane] : 0;
        #pragma unroll
        for (int o = 1; o < 32; o <<= 1) {
            int n = __shfl_up_sync(0xffffffffu, s, o);
            if (lane >= o) s += n;
        }
        swarp[lane] = s;
    }
    __syncthreads();
    if (wid > 0) v += swarp[wid - 1];
    return v;
}

// ---------------- prep: zero offs + split-transpose W1 + transpose W2 --------
__global__ void zero_prep_kernel(const float* __restrict__ W1, const float* __restrict__ W2, int L) {
    int b = blockIdx.x;
    if (b < NHID) {
        int n = b, k = threadIdx.x;      // 256 threads = 256 k
        float v = W1[(size_t)k * NHID + n];
        __nv_bfloat16 hi = __float2bfloat16(v);
        __nv_bfloat16 lo = __float2bfloat16(v - __bfloat162float(hi));
        g_Bhi[n * NFEAT + k] = hi;
        g_Blo[n * NFEAT + k] = lo;
    }
    if (b == gridDim.x - 1) {
        for (int i = threadIdx.x; i < NHID * NCLASS; i += blockDim.x) {
            int k = i >> 4, c = i & 15;
            g_W2t[c * NHID + k] = W2[i];
        }
    }
    int i = b * blockDim.x + threadIdx.x;
    if (i < L) g_offs[i] = 0;
}

// ---------------- CSR construction ----------------
__global__ void degree_kernel(const int* __restrict__ dst, int E) {
    int e = blockIdx.x * blockDim.x + threadIdx.x;
    if (e < E) atomicAdd(&g_offs[dst[e] + 1], 1);
}
__global__ void scan_block_sums(int L) {
    __shared__ int sw[32];
    int i = blockIdx.x * blockDim.x + threadIdx.x;
    int v = (i < L) ? g_offs[i] : 0;
    int incl = block_incl_scan(v, sw, blockDim.x >> 5);
    if (threadIdx.x == blockDim.x - 1) g_bsum[blockIdx.x] = incl;
}
__global__ void scan_partials(int NB) {
    __shared__ int sw[32];
    int t = threadIdx.x;
    int v = (t < NB) ? g_bsum[t] : 0;
    int incl = block_incl_scan(v, sw, blockDim.x >> 5);
    g_bexc[t] = incl - v;
}
__global__ void scan_apply(int L) {
    __shared__ int sw[32];
    int i = blockIdx.x * blockDim.x + threadIdx.x;
    int v = (i < L) ? g_offs[i] : 0;
    int incl = block_incl_scan(v, sw, blockDim.x >> 5);
    if (i < L) {
        int val = incl + g_bexc[blockIdx.x];
        g_offs[i] = val;
        if (i < L - 1) g_cursor[i] = val;
    }
}
__global__ void fill_csr(const int* __restrict__ src, const int* __restrict__ dst,
                         const float* __restrict__ w, int E) {
    int e = blockIdx.x * blockDim.x + threadIdx.x;
    if (e >= E) return;
    int d = dst[e];
    int p = atomicAdd(&g_cursor[d], 1);
    g_epair[p] = make_int2(src[e], __float_as_int(w[e]));
}

// ---------------- GEMM1: H0 = x @ W1 via bf16-split mma.sync -----------------
// 128x128 tile per CTA, 8 warps (4m x 2n), warp = 32x64 = 2x8 m16n8k16 tiles.
// K staged in 32-wide chunks. 3-term split: ah*bh + ah*bl + al*bh.
// __launch_bounds__(256, 2): cap regs at 128 so 2 CTAs co-reside per SM —
// cross-CTA overlap hides staging/sync latency (R6 profile: occ 12.4%, 1 CTA).
// B panels loaded with cp.async to overlap with A convert work.
#define ASTR 40

__global__ void __launch_bounds__(256, 2) gemm1_mma_kernel(const float* __restrict__ X, int N) {
    __shared__ __nv_bfloat16 sAh[128][ASTR];
    __shared__ __nv_bfloat16 sAl[128][ASTR];
    __shared__ __nv_bfloat16 sBh[128][ASTR];
    __shared__ __nv_bfloat16 sBl[128][ASTR];

    const int tid = threadIdx.x, lane = tid & 31, wid = tid >> 5;
    const int wm = wid >> 1, wn = wid & 1;          // warp grid 4x2
    const int r = lane >> 2, cc = (lane & 3) * 2;   // groupID / in-group k-pair
    const int bRow = blockIdx.x * 128;

    float acc[2][8][4];
    #pragma unroll
    for (int mt = 0; mt < 2; mt++)
        #pragma unroll
        for (int nt = 0; nt < 8; nt++)
            #pragma unroll
            for (int q = 0; q < 4; q++) acc[mt][nt][q] = 0.f;

    for (int kc = 0; kc < NFEAT; kc += 32) {
        // ---- B chunk via cp.async: 128 n x 32 k, hi+lo (overlaps A work) ----
        {
            int n = tid >> 1, kq = tid & 1;      // 2 x (16B pair) per row-half
            // each thread covers two kq positions: kq and kq+2
            #pragma unroll
            for (int j = 0; j < 2; j++) {
                int kqq = kq + j * 2;
                uint32_t dh = (uint32_t)__cvta_generic_to_shared(&sBh[n][kqq * 8]);
                uint32_t dl = (uint32_t)__cvta_generic_to_shared(&sBl[n][kqq * 8]);
                CP_ASYNC_16(dh, &g_Bhi[n * NFEAT + kc + kqq * 8]);
                CP_ASYNC_16(dl, &g_Blo[n * NFEAT + kc + kqq * 8]);
            }
            CP_ASYNC_COMMIT();
        }
        // ---- stage A chunk: 128 rows x 32 k, f32 -> bf16 hi/lo ----
        #pragma unroll
        for (int i = 0; i < 4; i++) {
            int slot = i * 256 + tid;           // 1024 float4 slots
            int row = slot >> 3, q = slot & 7;  // 8 float4 per row
            float4 v = make_float4(0.f, 0.f, 0.f, 0.f);
            if (bRow + row < N)
                v = *reinterpret_cast<const float4*>(&X[(size_t)(bRow + row) * NFEAT + kc + q * 4]);
            __nv_bfloat16 hx = __float2bfloat16(v.x), hy = __float2bfloat16(v.y);
            __nv_bfloat16 hz = __float2bfloat16(v.z), hw = __float2bfloat16(v.w);
            sAh[row][q * 4 + 0] = hx; sAh[row][q * 4 + 1] = hy;
            sAh[row][q * 4 + 2] = hz; sAh[row][q * 4 + 3] = hw;
            sAl[row][q * 4 + 0] = __float2bfloat16(v.x - __bfloat162float(hx));
            sAl[row][q * 4 + 1] = __float2bfloat16(v.y - __bfloat162float(hy));
            sAl[row][q * 4 + 2] = __float2bfloat16(v.z - __bfloat162float(hz));
            sAl[row][q * 4 + 3] = __float2bfloat16(v.w - __bfloat162float(hw));
        }
        CP_ASYNC_WAIT0();
        __syncthreads();

        #pragma unroll
        for (int ks = 0; ks < 32; ks += 16) {
            uint32_t Ah[2][4], Al[2][4];
            #pragma unroll
            for (int mt = 0; mt < 2; mt++) {
                int row0 = wm * 32 + mt * 16 + r;
                Ah[mt][0] = *reinterpret_cast<const uint32_t*>(&sAh[row0][ks + cc]);
                Ah[mt][1] = *reinterpret_cast<const uint32_t*>(&sAh[row0 + 8][ks + cc]);
                Ah[mt][2] = *reinterpret_cast<const uint32_t*>(&sAh[row0][ks + cc + 8]);
                Ah[mt][3] = *reinterpret_cast<const uint32_t*>(&sAh[row0 + 8][ks + cc + 8]);
                Al[mt][0] = *reinterpret_cast<const uint32_t*>(&sAl[row0][ks + cc]);
                Al[mt][1] = *reinterpret_cast<const uint32_t*>(&sAl[row0 + 8][ks + cc]);
                Al[mt][2] = *reinterpret_cast<const uint32_t*>(&sAl[row0][ks + cc + 8]);
                Al[mt][3] = *reinterpret_cast<const uint32_t*>(&sAl[row0 + 8][ks + cc + 8]);
            }
            #pragma unroll
            for (int nt = 0; nt < 8; nt++) {
                int n0 = wn * 64 + nt * 8 + r;   // B col = groupID
                uint32_t Bh[2], Bl[2];
                Bh[0] = *reinterpret_cast<const uint32_t*>(&sBh[n0][ks + cc]);
                Bh[1] = *reinterpret_cast<const uint32_t*>(&sBh[n0][ks + cc + 8]);
                Bl[0] = *reinterpret_cast<const uint32_t*>(&sBl[n0][ks + cc]);
                Bl[1] = *reinterpret_cast<const uint32_t*>(&sBl[n0][ks + cc + 8]);
                #pragma unroll
                for (int mt = 0; mt < 2; mt++) {
                    mma16816(acc[mt][nt], Ah[mt], Bh);
                    mma16816(acc[mt][nt], Ah[mt], Bl);
                    mma16816(acc[mt][nt], Al[mt], Bh);
                }
            }
        }
        __syncthreads();
    }

    // ---- epilogue ----
    #pragma unroll
    for (int mt = 0; mt < 2; mt++) {
        int row0 = bRow + wm * 32 + mt * 16 + r;
        #pragma unroll
        for (int nt = 0; nt < 8; nt++) {
            int col = wn * 64 + nt * 8 + cc;
            if (row0 < N)
                *reinterpret_cast<float2*>(&g_H0[(size_t)row0 * NHID + col]) =
                    make_float2(acc[mt][nt][0], acc[mt][nt][1]);
            if (row0 + 8 < N)
                *reinterpret_cast<float2*>(&g_H0[(size_t)(row0 + 8) * NHID + col]) =
                    make_float2(acc[mt][nt][2], acc[mt][nt][3]);
        }
    }
}

// ---------------- Fused SPMM1 + bias + relu + GEMM2 ----------------
__global__ void spmm1_gemm2_kernel(const float* __restrict__ b1, int N) {
    int warp = (blockIdx.x * blockDim.x + threadIdx.x) >> 5;
    int lane = threadIdx.x & 31;
    if (warp >= N) return;
    int beg = g_offs[warp], end = g_offs[warp + 1];
    const float4* H04 = reinterpret_cast<const float4*>(g_H0);
    float4 acc = make_float4(0.f, 0.f, 0.f, 0.f);
    int e = beg;
    for (; e + 1 < end; e += 2) {
        int2 p0 = g_epair[e], p1 = g_epair[e + 1];
        float w0 = __int_as_float(p0.y), w1 = __int_as_float(p1.y);
        float4 v0 = H04[(size_t)p0.x * 32 + lane];
        float4 v1 = H04[(size_t)p1.x * 32 + lane];
        acc.x = fmaf(w0, v0.x, acc.x); acc.y = fmaf(w0, v0.y, acc.y);
        acc.z = fmaf(w0, v0.z, acc.z); acc.w = fmaf(w0, v0.w, acc.w);
        acc.x = fmaf(w1, v1.x, acc.x); acc.y = fmaf(w1, v1.y, acc.y);
        acc.z = fmaf(w1, v1.z, acc.z); acc.w = fmaf(w1, v1.w, acc.w);
    }
    if (e < end) {
        int2 p0 = g_epair[e];
        float w0 = __int_as_float(p0.y);
        float4 v0 = H04[(size_t)p0.x * 32 + lane];
        acc.x = fmaf(w0, v0.x, acc.x); acc.y = fmaf(w0, v0.y, acc.y);
        acc.z = fmaf(w0, v0.z, acc.z); acc.w = fmaf(w0, v0.w, acc.w);
    }
    float4 bb = __ldg(&reinterpret_cast<const float4*>(b1)[lane]);
    float4 h;
    h.x = fmaxf(acc.x + bb.x, 0.f);
    h.y = fmaxf(acc.y + bb.y, 0.f);
    h.z = fmaxf(acc.z + bb.z, 0.f);
    h.w = fmaxf(acc.w + bb.w, 0.f);

    const float4* W2t4 = reinterpret_cast<const float4*>(g_W2t);
    float p[16];
    #pragma unroll
    for (int c = 0; c < 16; c++) {
        float4 wv = __ldg(&W2t4[c * 32 + lane]);
        float t = h.x * wv.x;
        t = fmaf(h.y, wv.y, t);
        t = fmaf(h.z, wv.z, t);
        t = fmaf(h.w, wv.w, t);
        p[c] = t;
    }
    {   bool hi = (lane & 1);
        #pragma unroll
        for (int k = 0; k < 8; k++) {
            float send = hi ? p[k] : p[k + 8];
            float recv = __shfl_xor_sync(0xffffffffu, send, 1);
            p[k] = (hi ? p[k + 8] : p[k]) + recv;
        }
    }
    {   bool hi = (lane & 2);
        #pragma unroll
        for (int k = 0; k < 4; k++) {
            float send = hi ? p[k] : p[k + 4];
            float recv = __shfl_xor_sync(0xffffffffu, send, 2);
            p[k] = (hi ? p[k + 4] : p[k]) + recv;
        }
    }
    {   bool hi = (lane & 4);
        #pragma unroll
        for (int k = 0; k < 2; k++) {
            float send = hi ? p[k] : p[k + 2];
            float recv = __shfl_xor_sync(0xffffffffu, send, 4);
            p[k] = (hi ? p[k + 2] : p[k]) + recv;
        }
    }
    {   bool hi = (lane & 8);
        float send = hi ? p[0] : p[1];
        float recv = __shfl_xor_sync(0xffffffffu, send, 8);
        p[0] = (hi ? p[1] : p[0]) + recv;
    }
    p[0] += __shfl_xor_sync(0xffffffffu, p[0], 16);
    int c = ((lane & 1) << 3) | ((lane & 2) << 1) | ((lane & 4) >> 1) | ((lane & 8) >> 3);
    if (lane < 16) g_H2[(size_t)warp * NCLASS + c] = p[0];
}

// ---------------- SPMM2 + bias + log_softmax ----------------
__global__ void spmm2_kernel(const float* __restrict__ b2, float* __restrict__ out, int N) {
    int gwarp = (blockIdx.x * blockDim.x + threadIdx.x) >> 5;
    int lane = threadIdx.x & 31;
    int half = lane >> 4, l = lane & 15;
    int row = gwarp * 2 + half;
    float acc = 0.f;
    if (row < N) {
        int beg = g_offs[row], end = g_offs[row + 1];
        for (int e = beg; e < end; e++) {
            int2 pe = g_epair[e];
            float w = __int_as_float(pe.y);
            acc = fmaf(w, __ldg(&g_H2[(size_t)pe.x * NCLASS + l]), acc);
        }
    }
    acc += b2[l];
    float m = acc;
    #pragma unroll
    for (int o = 8; o > 0; o >>= 1) m = fmaxf(m, __shfl_xor_sync(0xffffffffu, m, o, 16));
    float ex = expf(acc - m);
    float s = ex;
    #pragma unroll
    for (int o = 8; o > 0; o >>= 1) s += __shfl_xor_sync(0xffffffffu, s, o, 16);
    if (row < N) out[(size_t)row * NCLASS + l] = acc - m - logf(s);
}

// ---------------- launch ----------------
extern "C" void kernel_launch(void* const* d_in, const int* in_sizes, int n_in,
                              void* d_out, int out_size) {
    const float* x   = (const float*)d_in[0];
    const float* W1  = (const float*)d_in[1];
    const float* b1  = (const float*)d_in[2];
    const float* W2  = (const float*)d_in[3];
    const float* b2  = (const float*)d_in[4];
    const float* ew  = (const float*)d_in[5];
    const int*   src = (const int*)d_in[6];
    const int*   dst = (const int*)d_in[7];
    float* out = (float*)d_out;

    const int N = in_sizes[0] / NFEAT;
    const int E = in_sizes[5];
    const int L = N + 1;
    const int NB = (L + 255) / 256;   // <= 512

    zero_prep_kernel<<<NB, 256>>>(W1, W2, L);                     // 1
    degree_kernel<<<(E + 255) / 256, 256>>>(dst, E);              // 2
    scan_block_sums<<<NB, 256>>>(L);                              // 3
    gemm1_mma_kernel<<<(N + 127) / 128, 256>>>(x, N);             // 4 <- profiled
    scan_partials<<<1, 512>>>(NB);                                // 5
    scan_apply<<<NB, 256>>>(L);                                   // 6
    fill_csr<<<(E + 255) / 256, 256>>>(src, dst, ew, E);          // 7
    spmm1_gemm2_kernel<<<(N + 7) / 8, 256>>>(b1, N);              // 8
    spmm2_kernel<<<(N + 15) / 16, 256>>>(b2, out, N);             // 9
}

// round 8
// speedup vs baseline: 1.6638x; 1.1095x over previous
#include <cuda_runtime.h>
#include <cuda_bf16.h>
#include <cuda_fp16.h>
#include <math.h>
#include <stdint.h>

#define NFEAT 256
#define NHID  128
#define NCLASS 16
#define MAXN 100000
#define MAXE 3200000

// ---------------- device scratch (static allocation, allowed) ----------------
__device__ __half g_H0[(size_t)MAXN * NHID];  // x @ W1, fp16 (halves SPMM gather)
__device__ float g_H2[(size_t)MAXN * NCLASS]; // spmm1 -> relu -> @W2 (fused)
__device__ float g_W2t[NCLASS * NHID];        // W2 transposed [16][128]
__device__ __nv_bfloat16 g_Bhi[NHID * NFEAT]; // W1^T split-high [n][k]
__device__ __nv_bfloat16 g_Blo[NHID * NFEAT]; // W1^T split-low  [n][k]
__device__ int   g_offs[MAXN + 1];
__device__ int   g_cursor[MAXN];
__device__ int2  g_epair[MAXE];               // (src, weight-bits), CSR order
__device__ int   g_bsum[512];
__device__ int   g_bexc[512];

// ---------------- mma.sync m16n8k16 bf16 (sm_80+ baseline, sm_103-safe) -----
__device__ __forceinline__ void mma16816(float* c, const uint32_t* a, const uint32_t* b) {
    asm volatile("mma.sync.aligned.m16n8k16.row.col.f32.bf16.bf16.f32 "
                 "{%0,%1,%2,%3}, {%4,%5,%6,%7}, {%8,%9}, {%0,%1,%2,%3};"
                 : "+f"(c[0]), "+f"(c[1]), "+f"(c[2]), "+f"(c[3])
                 : "r"(a[0]), "r"(a[1]), "r"(a[2]), "r"(a[3]),
                   "r"(b[0]), "r"(b[1]));
}

#define CP_ASYNC_16(smem_u32, gptr) \
    asm volatile("cp.async.cg.shared.global [%0], [%1], 16;" \
                 :: "r"(smem_u32), "l"(gptr) : "memory")
#define CP_ASYNC_COMMIT() asm volatile("cp.async.commit_group;" ::: "memory")
#define CP_ASYNC_WAIT0()  asm volatile("cp.async.wait_group 0;" ::: "memory")

// ---------------- scan helper ----------------
__device__ __forceinline__ int block_incl_scan(int v, int* swarp, int nwarps) {
    int lane = threadIdx.x & 31, wid = threadIdx.x >> 5;
    #pragma unroll
    for (int o = 1; o < 32; o <<= 1) {
        int n = __shfl_up_sync(0xffffffffu, v, o);
        if (lane >= o) v += n;
    }
    if (lane == 31) swarp[wid] = v;
    __syncthreads();
    if (wid == 0) {
        int s = (lane < nwarps) ? swarp[lane] : 0;
        #pragma unroll
        for (int o = 1; o < 32; o <<= 1) {
            int n = __shfl_up_sync(0xffffffffu, s, o);
            if (lane >= o) s += n;
        }
        swarp[lane] = s;
    }
    __syncthreads();
    if (wid > 0) v += swarp[wid - 1];
    return v;
}

// ---------------- prep: zero offs + split-transpose W1 + transpose W2 --------
__global__ void zero_prep_kernel(const float* __restrict__ W1, const float* __restrict__ W2, int L) {
    int b = blockIdx.x;
    if (b < NHID) {
        int n = b, k = threadIdx.x;      // 256 threads = 256 k
        float v = W1[(size_t)k * NHID + n];
        __nv_bfloat16 hi = __float2bfloat16(v);
        __nv_bfloat16 lo = __float2bfloat16(v - __bfloat162float(hi));
        g_Bhi[n * NFEAT + k] = hi;
        g_Blo[n * NFEAT + k] = lo;
    }
    if (b == gridDim.x - 1) {
        for (int i = threadIdx.x; i < NHID * NCLASS; i += blockDim.x) {
            int k = i >> 4, c = i & 15;
            g_W2t[c * NHID + k] = W2[i];
        }
    }
    int i = b * blockDim.x + threadIdx.x;
    if (i < L) g_offs[i] = 0;
}

// ---------------- CSR construction ----------------
__global__ void degree_kernel(const int* __restrict__ dst, int E) {
    int e = blockIdx.x * blockDim.x + threadIdx.x;
    if (e < E) atomicAdd(&g_offs[dst[e] + 1], 1);
}
__global__ void scan_block_sums(int L) {
    __shared__ int sw[32];
    int i = blockIdx.x * blockDim.x + threadIdx.x;
    int v = (i < L) ? g_offs[i] : 0;
    int incl = block_incl_scan(v, sw, blockDim.x >> 5);
    if (threadIdx.x == blockDim.x - 1) g_bsum[blockIdx.x] = incl;
}
__global__ void scan_partials(int NB) {
    __shared__ int sw[32];
    int t = threadIdx.x;
    int v = (t < NB) ? g_bsum[t] : 0;
    int incl = block_incl_scan(v, sw, blockDim.x >> 5);
    g_bexc[t] = incl - v;
}
__global__ void scan_apply(int L) {
    __shared__ int sw[32];
    int i = blockIdx.x * blockDim.x + threadIdx.x;
    int v = (i < L) ? g_offs[i] : 0;
    int incl = block_incl_scan(v, sw, blockDim.x >> 5);
    if (i < L) {
        int val = incl + g_bexc[blockIdx.x];
        g_offs[i] = val;
        if (i < L - 1) g_cursor[i] = val;
    }
}
__global__ void fill_csr(const int* __restrict__ src, const int* __restrict__ dst,
                         const float* __restrict__ w, int E) {
    int e = blockIdx.x * blockDim.x + threadIdx.x;
    if (e >= E) return;
    int d = dst[e];
    int p = atomicAdd(&g_cursor[d], 1);
    g_epair[p] = make_int2(src[e], __float_as_int(w[e]));
}

// ---------------- GEMM1: H0 = x @ W1 via bf16-split mma.sync -----------------
// 128x128 tile per CTA, 8 warps (4m x 2n), warp = 32x64 = 2x8 m16n8k16 tiles.
// K staged in 32-wide chunks. 3-term split: ah*bh + ah*bl + al*bh.
// __launch_bounds__(256, 2): 2 CTAs/SM for cross-CTA latency hiding.
#define ASTR 40

__global__ void __launch_bounds__(256, 2) gemm1_mma_kernel(const float* __restrict__ X, int N) {
    __shared__ __nv_bfloat16 sAh[128][ASTR];
    __shared__ __nv_bfloat16 sAl[128][ASTR];
    __shared__ __nv_bfloat16 sBh[128][ASTR];
    __shared__ __nv_bfloat16 sBl[128][ASTR];

    const int tid = threadIdx.x, lane = tid & 31, wid = tid >> 5;
    const int wm = wid >> 1, wn = wid & 1;          // warp grid 4x2
    const int r = lane >> 2, cc = (lane & 3) * 2;   // groupID / in-group k-pair
    const int bRow = blockIdx.x * 128;

    float acc[2][8][4];
    #pragma unroll
    for (int mt = 0; mt < 2; mt++)
        #pragma unroll
        for (int nt = 0; nt < 8; nt++)
            #pragma unroll
            for (int q = 0; q < 4; q++) acc[mt][nt][q] = 0.f;

    for (int kc = 0; kc < NFEAT; kc += 32) {
        // ---- B chunk via cp.async: 128 n x 32 k, hi+lo (overlaps A work) ----
        {
            int n = tid >> 1, kq = tid & 1;
            #pragma unroll
            for (int j = 0; j < 2; j++) {
                int kqq = kq + j * 2;
                uint32_t dh = (uint32_t)__cvta_generic_to_shared(&sBh[n][kqq * 8]);
                uint32_t dl = (uint32_t)__cvta_generic_to_shared(&sBl[n][kqq * 8]);
                CP_ASYNC_16(dh, &g_Bhi[n * NFEAT + kc + kqq * 8]);
                CP_ASYNC_16(dl, &g_Blo[n * NFEAT + kc + kqq * 8]);
            }
            CP_ASYNC_COMMIT();
        }
        // ---- stage A chunk: 128 rows x 32 k, f32 -> bf16 hi/lo ----
        #pragma unroll
        for (int i = 0; i < 4; i++) {
            int slot = i * 256 + tid;           // 1024 float4 slots
            int row = slot >> 3, q = slot & 7;  // 8 float4 per row
            float4 v = make_float4(0.f, 0.f, 0.f, 0.f);
            if (bRow + row < N)
                v = *reinterpret_cast<const float4*>(&X[(size_t)(bRow + row) * NFEAT + kc + q * 4]);
            __nv_bfloat16 hx = __float2bfloat16(v.x), hy = __float2bfloat16(v.y);
            __nv_bfloat16 hz = __float2bfloat16(v.z), hw = __float2bfloat16(v.w);
            sAh[row][q * 4 + 0] = hx; sAh[row][q * 4 + 1] = hy;
            sAh[row][q * 4 + 2] = hz; sAh[row][q * 4 + 3] = hw;
            sAl[row][q * 4 + 0] = __float2bfloat16(v.x - __bfloat162float(hx));
            sAl[row][q * 4 + 1] = __float2bfloat16(v.y - __bfloat162float(hy));
            sAl[row][q * 4 + 2] = __float2bfloat16(v.z - __bfloat162float(hz));
            sAl[row][q * 4 + 3] = __float2bfloat16(v.w - __bfloat162float(hw));
        }
        CP_ASYNC_WAIT0();
        __syncthreads();

        #pragma unroll
        for (int ks = 0; ks < 32; ks += 16) {
            uint32_t Ah[2][4], Al[2][4];
            #pragma unroll
            for (int mt = 0; mt < 2; mt++) {
                int row0 = wm * 32 + mt * 16 + r;
                Ah[mt][0] = *reinterpret_cast<const uint32_t*>(&sAh[row0][ks + cc]);
                Ah[mt][1] = *reinterpret_cast<const uint32_t*>(&sAh[row0 + 8][ks + cc]);
                Ah[mt][2] = *reinterpret_cast<const uint32_t*>(&sAh[row0][ks + cc + 8]);
                Ah[mt][3] = *reinterpret_cast<const uint32_t*>(&sAh[row0 + 8][ks + cc + 8]);
                Al[mt][0] = *reinterpret_cast<const uint32_t*>(&sAl[row0][ks + cc]);
                Al[mt][1] = *reinterpret_cast<const uint32_t*>(&sAl[row0 + 8][ks + cc]);
                Al[mt][2] = *reinterpret_cast<const uint32_t*>(&sAl[row0][ks + cc + 8]);
                Al[mt][3] = *reinterpret_cast<const uint32_t*>(&sAl[row0 + 8][ks + cc + 8]);
            }
            #pragma unroll
            for (int nt = 0; nt < 8; nt++) {
                int n0 = wn * 64 + nt * 8 + r;   // B col = groupID
                uint32_t Bh[2], Bl[2];
                Bh[0] = *reinterpret_cast<const uint32_t*>(&sBh[n0][ks + cc]);
                Bh[1] = *reinterpret_cast<const uint32_t*>(&sBh[n0][ks + cc + 8]);
                Bl[0] = *reinterpret_cast<const uint32_t*>(&sBl[n0][ks + cc]);
                Bl[1] = *reinterpret_cast<const uint32_t*>(&sBl[n0][ks + cc + 8]);
                #pragma unroll
                for (int mt = 0; mt < 2; mt++) {
                    mma16816(acc[mt][nt], Ah[mt], Bh);
                    mma16816(acc[mt][nt], Ah[mt], Bl);
                    mma16816(acc[mt][nt], Al[mt], Bh);
                }
            }
        }
        __syncthreads();
    }

    // ---- epilogue: fp16 H0 ----
    #pragma unroll
    for (int mt = 0; mt < 2; mt++) {
        int row0 = bRow + wm * 32 + mt * 16 + r;
        #pragma unroll
        for (int nt = 0; nt < 8; nt++) {
            int col = wn * 64 + nt * 8 + cc;     // cc even -> 4B aligned
            if (row0 < N)
                *reinterpret_cast<__half2*>(&g_H0[(size_t)row0 * NHID + col]) =
                    __floats2half2_rn(acc[mt][nt][0], acc[mt][nt][1]);
            if (row0 + 8 < N)
                *reinterpret_cast<__half2*>(&g_H0[(size_t)(row0 + 8) * NHID + col]) =
                    __floats2half2_rn(acc[mt][nt][2], acc[mt][nt][3]);
        }
    }
}

// ---------------- Fused SPMM1 + bias + relu + GEMM2 ----------------
// warp per dst row; lane holds 4 cols (one 8B fp16x4 load per edge).
__device__ __forceinline__ void fma_h4(float4& acc, float w, uint2 u) {
    float2 f0 = __half22float2(*reinterpret_cast<__half2*>(&u.x));
    float2 f1 = __half22float2(*reinterpret_cast<__half2*>(&u.y));
    acc.x = fmaf(w, f0.x, acc.x); acc.y = fmaf(w, f0.y, acc.y);
    acc.z = fmaf(w, f1.x, acc.z); acc.w = fmaf(w, f1.y, acc.w);
}

__global__ void spmm1_gemm2_kernel(const float* __restrict__ b1, int N) {
    int warp = (blockIdx.x * blockDim.x + threadIdx.x) >> 5;
    int lane = threadIdx.x & 31;
    if (warp >= N) return;
    int beg = g_offs[warp], end = g_offs[warp + 1];
    const uint2* H0v = reinterpret_cast<const uint2*>(g_H0);  // 4 halves per elem
    float4 acc = make_float4(0.f, 0.f, 0.f, 0.f);
    int e = beg;
    for (; e + 1 < end; e += 2) {
        int2 p0 = g_epair[e], p1 = g_epair[e + 1];
        float w0 = __int_as_float(p0.y), w1 = __int_as_float(p1.y);
        uint2 v0 = H0v[(size_t)p0.x * 32 + lane];
        uint2 v1 = H0v[(size_t)p1.x * 32 + lane];
        fma_h4(acc, w0, v0);
        fma_h4(acc, w1, v1);
    }
    if (e < end) {
        int2 p0 = g_epair[e];
        uint2 v0 = H0v[(size_t)p0.x * 32 + lane];
        fma_h4(acc, __int_as_float(p0.y), v0);
    }
    float4 bb = __ldg(&reinterpret_cast<const float4*>(b1)[lane]);
    float4 h;
    h.x = fmaxf(acc.x + bb.x, 0.f);
    h.y = fmaxf(acc.y + bb.y, 0.f);
    h.z = fmaxf(acc.z + bb.z, 0.f);
    h.w = fmaxf(acc.w + bb.w, 0.f);

    const float4* W2t4 = reinterpret_cast<const float4*>(g_W2t);
    float p[16];
    #pragma unroll
    for (int c = 0; c < 16; c++) {
        float4 wv = __ldg(&W2t4[c * 32 + lane]);
        float t = h.x * wv.x;
        t = fmaf(h.y, wv.y, t);
        t = fmaf(h.z, wv.z, t);
        t = fmaf(h.w, wv.w, t);
        p[c] = t;
    }
    {   bool hi = (lane & 1);
        #pragma unroll
        for (int k = 0; k < 8; k++) {
            float send = hi ? p[k] : p[k + 8];
            float recv = __shfl_xor_sync(0xffffffffu, send, 1);
            p[k] = (hi ? p[k + 8] : p[k]) + recv;
        }
    }
    {   bool hi = (lane & 2);
        #pragma unroll
        for (int k = 0; k < 4; k++) {
            float send = hi ? p[k] : p[k + 4];
            float recv = __shfl_xor_sync(0xffffffffu, send, 2);
            p[k] = (hi ? p[k + 4] : p[k]) + recv;
        }
    }
    {   bool hi = (lane & 4);
        #pragma unroll
        for (int k = 0; k < 2; k++) {
            float send = hi ? p[k] : p[k + 2];
            float recv = __shfl_xor_sync(0xffffffffu, send, 4);
            p[k] = (hi ? p[k + 2] : p[k]) + recv;
        }
    }
    {   bool hi = (lane & 8);
        float send = hi ? p[0] : p[1];
        float recv = __shfl_xor_sync(0xffffffffu, send, 8);
        p[0] = (hi ? p[1] : p[0]) + recv;
    }
    p[0] += __shfl_xor_sync(0xffffffffu, p[0], 16);
    int c = ((lane & 1) << 3) | ((lane & 2) << 1) | ((lane & 4) >> 1) | ((lane & 8) >> 3);
    if (lane < 16) g_H2[(size_t)warp * NCLASS + c] = p[0];
}

// ---------------- SPMM2 + bias + log_softmax ----------------
__global__ void spmm2_kernel(const float* __restrict__ b2, float* __restrict__ out, int N) {
    int gwarp = (blockIdx.x * blockDim.x + threadIdx.x) >> 5;
    int lane = threadIdx.x & 31;
    int half = lane >> 4, l = lane & 15;
    int row = gwarp * 2 + half;
    float acc = 0.f;
    if (row < N) {
        int beg = g_offs[row], end = g_offs[row + 1];
        for (int e = beg; e < end; e++) {
            int2 pe = g_epair[e];
            float w = __int_as_float(pe.y);
            acc = fmaf(w, __ldg(&g_H2[(size_t)pe.x * NCLASS + l]), acc);
        }
    }
    acc += b2[l];
    float m = acc;
    #pragma unroll
    for (int o = 8; o > 0; o >>= 1) m = fmaxf(m, __shfl_xor_sync(0xffffffffu, m, o, 16));
    float ex = expf(acc - m);
    float s = ex;
    #pragma unroll
    for (int o = 8; o > 0; o >>= 1) s += __shfl_xor_sync(0xffffffffu, s, o, 16);
    if (row < N) out[(size_t)row * NCLASS + l] = acc - m - logf(s);
}

// ---------------- launch ----------------
extern "C" void kernel_launch(void* const* d_in, const int* in_sizes, int n_in,
                              void* d_out, int out_size) {
    const float* x   = (const float*)d_in[0];
    const float* W1  = (const float*)d_in[1];
    const float* b1  = (const float*)d_in[2];
    const float* W2  = (const float*)d_in[3];
    const float* b2  = (const float*)d_in[4];
    const float* ew  = (const float*)d_in[5];
    const int*   src = (const int*)d_in[6];
    const int*   dst = (const int*)d_in[7];
    float* out = (float*)d_out;

    const int N = in_sizes[0] / NFEAT;
    const int E = in_sizes[5];
    const int L = N + 1;
    const int NB = (L + 255) / 256;   // <= 512

    zero_prep_kernel<<<NB, 256>>>(W1, W2, L);                     // 1
    degree_kernel<<<(E + 255) / 256, 256>>>(dst, E);              // 2
    scan_block_sums<<<NB, 256>>>(L);                              // 3
    gemm1_mma_kernel<<<(N + 127) / 128, 256>>>(x, N);             // 4 <- profiled
    scan_partials<<<1, 512>>>(NB);                                // 5
    scan_apply<<<NB, 256>>>(L);                                   // 6
    fill_csr<<<(E + 255) / 256, 256>>>(src, dst, ew, E);          // 7
    spmm1_gemm2_kernel<<<(N + 7) / 8, 256>>>(b1, N);              // 8
    spmm2_kernel<<<(N + 15) / 16, 256>>>(b2, out, N);             // 9
}

// round 9
// speedup vs baseline: 1.7985x; 1.0810x over previous
#include <cuda_runtime.h>
#include <cuda_bf16.h>
#include <cuda_fp16.h>
#include <math.h>
#include <stdint.h>

#define NFEAT 256
#define NHID  128
#define NCLASS 16
#define MAXN 100000
#define MAXE 3200000

// ---------------- device scratch (static allocation, allowed) ----------------
__device__ __half g_H0[(size_t)MAXN * NHID];  // x @ W1, fp16 (halves SPMM gather)
__device__ float g_H2[(size_t)MAXN * NCLASS]; // spmm1 -> relu -> @W2 (fused)
__device__ float g_W2t[NCLASS * NHID];        // W2 transposed [16][128]
__device__ __nv_bfloat16 g_Bhi[NHID * NFEAT]; // W1^T split-high [n][k]
__device__ __nv_bfloat16 g_Blo[NHID * NFEAT]; // W1^T split-low  [n][k]
__device__ int   g_offs[MAXN + 1];
__device__ int   g_cursor[MAXN];
__device__ int2  g_epair[MAXE];               // (src, weight-bits), CSR order
__device__ int   g_bsum[512];
__device__ int   g_bexc[512];

// ---------------- mma.sync m16n8k16 bf16 (sm_80+ baseline, sm_103-safe) -----
__device__ __forceinline__ void mma16816(float* c, const uint32_t* a, const uint32_t* b) {
    asm volatile("mma.sync.aligned.m16n8k16.row.col.f32.bf16.bf16.f32 "
                 "{%0,%1,%2,%3}, {%4,%5,%6,%7}, {%8,%9}, {%0,%1,%2,%3};"
                 : "+f"(c[0]), "+f"(c[1]), "+f"(c[2]), "+f"(c[3])
                 : "r"(a[0]), "r"(a[1]), "r"(a[2]), "r"(a[3]),
                   "r"(b[0]), "r"(b[1]));
}

#define CP_ASYNC_16(smem_u32, gptr) \
    asm volatile("cp.async.cg.shared.global [%0], [%1], 16;" \
                 :: "r"(smem_u32), "l"(gptr) : "memory")
#define CP_ASYNC_COMMIT() asm volatile("cp.async.commit_group;" ::: "memory")
#define CP_ASYNC_WAIT0()  asm volatile("cp.async.wait_group 0;" ::: "memory")

// ---------------- scan helper ----------------
__device__ __forceinline__ int block_incl_scan(int v, int* swarp, int nwarps) {
    int lane = threadIdx.x & 31, wid = threadIdx.x >> 5;
    #pragma unroll
    for (int o = 1; o < 32; o <<= 1) {
        int n = __shfl_up_sync(0xffffffffu, v, o);
        if (lane >= o) v += n;
    }
    if (lane == 31) swarp[wid] = v;
    __syncthreads();
    if (wid == 0) {
        int s = (lane < nwarps) ? swarp[lane] : 0;
        #pragma unroll
        for (int o = 1; o < 32; o <<= 1) {
            int n = __shfl_up_sync(0xffffffffu, s, o);
            if (lane >= o) s += n;
        }
        swarp[lane] = s;
    }
    __syncthreads();
    if (wid > 0) v += swarp[wid - 1];
    return v;
}

// ---------------- prep: zero offs + split-transpose W1 + transpose W2 --------
__global__ void zero_prep_kernel(const float* __restrict__ W1, const float* __restrict__ W2, int L) {
    int b = blockIdx.x;
    if (b < NHID) {
        int n = b, k = threadIdx.x;      // 256 threads = 256 k
        float v = W1[(size_t)k * NHID + n];
        __nv_bfloat16 hi = __float2bfloat16(v);
        __nv_bfloat16 lo = __float2bfloat16(v - __bfloat162float(hi));
        g_Bhi[n * NFEAT + k] = hi;
        g_Blo[n * NFEAT + k] = lo;
    }
    if (b == gridDim.x - 1) {
        for (int i = threadIdx.x; i < NHID * NCLASS; i += blockDim.x) {
            int k = i >> 4, c = i & 15;
            g_W2t[c * NHID + k] = W2[i];
        }
    }
    int i = b * blockDim.x + threadIdx.x;
    if (i < L) g_offs[i] = 0;
}

// ---------------- CSR construction ----------------
__global__ void degree_kernel(const int* __restrict__ dst, int E) {
    int e = blockIdx.x * blockDim.x + threadIdx.x;
    if (e < E) atomicAdd(&g_offs[dst[e] + 1], 1);
}
__global__ void scan_block_sums(int L) {
    __shared__ int sw[32];
    int i = blockIdx.x * blockDim.x + threadIdx.x;
    int v = (i < L) ? g_offs[i] : 0;
    int incl = block_incl_scan(v, sw, blockDim.x >> 5);
    if (threadIdx.x == blockDim.x - 1) g_bsum[blockIdx.x] = incl;
}
__global__ void scan_partials(int NB) {
    __shared__ int sw[32];
    int t = threadIdx.x;
    int v = (t < NB) ? g_bsum[t] : 0;
    int incl = block_incl_scan(v, sw, blockDim.x >> 5);
    g_bexc[t] = incl - v;
}
__global__ void scan_apply(int L) {
    __shared__ int sw[32];
    int i = blockIdx.x * blockDim.x + threadIdx.x;
    int v = (i < L) ? g_offs[i] : 0;
    int incl = block_incl_scan(v, sw, blockDim.x >> 5);
    if (i < L) {
        int val = incl + g_bexc[blockIdx.x];
        g_offs[i] = val;
        if (i < L - 1) g_cursor[i] = val;
    }
}
__global__ void fill_csr(const int* __restrict__ src, const int* __restrict__ dst,
                         const float* __restrict__ w, int E) {
    int e = blockIdx.x * blockDim.x + threadIdx.x;
    if (e >= E) return;
    int d = dst[e];
    int p = atomicAdd(&g_cursor[d], 1);
    g_epair[p] = make_int2(src[e], __float_as_int(w[e]));
}

// ---------------- GEMM1: H0 = x @ W1 via bf16-split mma.sync -----------------
#define ASTR 40

__global__ void __launch_bounds__(256, 2) gemm1_mma_kernel(const float* __restrict__ X, int N) {
    __shared__ __nv_bfloat16 sAh[128][ASTR];
    __shared__ __nv_bfloat16 sAl[128][ASTR];
    __shared__ __nv_bfloat16 sBh[128][ASTR];
    __shared__ __nv_bfloat16 sBl[128][ASTR];

    const int tid = threadIdx.x, lane = tid & 31, wid = tid >> 5;
    const int wm = wid >> 1, wn = wid & 1;          // warp grid 4x2
    const int r = lane >> 2, cc = (lane & 3) * 2;   // groupID / in-group k-pair
    const int bRow = blockIdx.x * 128;

    float acc[2][8][4];
    #pragma unroll
    for (int mt = 0; mt < 2; mt++)
        #pragma unroll
        for (int nt = 0; nt < 8; nt++)
            #pragma unroll
            for (int q = 0; q < 4; q++) acc[mt][nt][q] = 0.f;

    for (int kc = 0; kc < NFEAT; kc += 32) {
        // ---- B chunk via cp.async (overlaps A convert work) ----
        {
            int n = tid >> 1, kq = tid & 1;
            #pragma unroll
            for (int j = 0; j < 2; j++) {
                int kqq = kq + j * 2;
                uint32_t dh = (uint32_t)__cvta_generic_to_shared(&sBh[n][kqq * 8]);
                uint32_t dl = (uint32_t)__cvta_generic_to_shared(&sBl[n][kqq * 8]);
                CP_ASYNC_16(dh, &g_Bhi[n * NFEAT + kc + kqq * 8]);
                CP_ASYNC_16(dl, &g_Blo[n * NFEAT + kc + kqq * 8]);
            }
            CP_ASYNC_COMMIT();
        }
        // ---- stage A chunk: 128 rows x 32 k, f32 -> bf16 hi/lo ----
        #pragma unroll
        for (int i = 0; i < 4; i++) {
            int slot = i * 256 + tid;
            int row = slot >> 3, q = slot & 7;
            float4 v = make_float4(0.f, 0.f, 0.f, 0.f);
            if (bRow + row < N)
                v = *reinterpret_cast<const float4*>(&X[(size_t)(bRow + row) * NFEAT + kc + q * 4]);
            __nv_bfloat16 hx = __float2bfloat16(v.x), hy = __float2bfloat16(v.y);
            __nv_bfloat16 hz = __float2bfloat16(v.z), hw = __float2bfloat16(v.w);
            sAh[row][q * 4 + 0] = hx; sAh[row][q * 4 + 1] = hy;
            sAh[row][q * 4 + 2] = hz; sAh[row][q * 4 + 3] = hw;
            sAl[row][q * 4 + 0] = __float2bfloat16(v.x - __bfloat162float(hx));
            sAl[row][q * 4 + 1] = __float2bfloat16(v.y - __bfloat162float(hy));
            sAl[row][q * 4 + 2] = __float2bfloat16(v.z - __bfloat162float(hz));
            sAl[row][q * 4 + 3] = __float2bfloat16(v.w - __bfloat162float(hw));
        }
        CP_ASYNC_WAIT0();
        __syncthreads();

        #pragma unroll
        for (int ks = 0; ks < 32; ks += 16) {
            uint32_t Ah[2][4], Al[2][4];
            #pragma unroll
            for (int mt = 0; mt < 2; mt++) {
                int row0 = wm * 32 + mt * 16 + r;
                Ah[mt][0] = *reinterpret_cast<const uint32_t*>(&sAh[row0][ks + cc]);
                Ah[mt][1] = *reinterpret_cast<const uint32_t*>(&sAh[row0 + 8][ks + cc]);
                Ah[mt][2] = *reinterpret_cast<const uint32_t*>(&sAh[row0][ks + cc + 8]);
                Ah[mt][3] = *reinterpret_cast<const uint32_t*>(&sAh[row0 + 8][ks + cc + 8]);
                Al[mt][0] = *reinterpret_cast<const uint32_t*>(&sAl[row0][ks + cc]);
                Al[mt][1] = *reinterpret_cast<const uint32_t*>(&sAl[row0 + 8][ks + cc]);
                Al[mt][2] = *reinterpret_cast<const uint32_t*>(&sAl[row0][ks + cc + 8]);
                Al[mt][3] = *reinterpret_cast<const uint32_t*>(&sAl[row0 + 8][ks + cc + 8]);
            }
            #pragma unroll
            for (int nt = 0; nt < 8; nt++) {
                int n0 = wn * 64 + nt * 8 + r;
                uint32_t Bh[2], Bl[2];
                Bh[0] = *reinterpret_cast<const uint32_t*>(&sBh[n0][ks + cc]);
                Bh[1] = *reinterpret_cast<const uint32_t*>(&sBh[n0][ks + cc + 8]);
                Bl[0] = *reinterpret_cast<const uint32_t*>(&sBl[n0][ks + cc]);
                Bl[1] = *reinterpret_cast<const uint32_t*>(&sBl[n0][ks + cc + 8]);
                #pragma unroll
                for (int mt = 0; mt < 2; mt++) {
                    mma16816(acc[mt][nt], Ah[mt], Bh);
                    mma16816(acc[mt][nt], Ah[mt], Bl);
                    mma16816(acc[mt][nt], Al[mt], Bh);
                }
            }
        }
        __syncthreads();
    }

    // ---- epilogue: fp16 H0 ----
    #pragma unroll
    for (int mt = 0; mt < 2; mt++) {
        int row0 = bRow + wm * 32 + mt * 16 + r;
        #pragma unroll
        for (int nt = 0; nt < 8; nt++) {
            int col = wn * 64 + nt * 8 + cc;
            if (row0 < N)
                *reinterpret_cast<__half2*>(&g_H0[(size_t)row0 * NHID + col]) =
                    __floats2half2_rn(acc[mt][nt][0], acc[mt][nt][1]);
            if (row0 + 8 < N)
                *reinterpret_cast<__half2*>(&g_H0[(size_t)(row0 + 8) * NHID + col]) =
                    __floats2half2_rn(acc[mt][nt][2], acc[mt][nt][3]);
        }
    }
}

// ---------------- Fused SPMM1 + bias + relu + GEMM2 ----------------
__device__ __forceinline__ void fma_h4(float4& acc, float w, uint2 u) {
    float2 f0 = __half22float2(*reinterpret_cast<__half2*>(&u.x));
    float2 f1 = __half22float2(*reinterpret_cast<__half2*>(&u.y));
    acc.x = fmaf(w, f0.x, acc.x); acc.y = fmaf(w, f0.y, acc.y);
    acc.z = fmaf(w, f1.x, acc.z); acc.w = fmaf(w, f1.y, acc.w);
}

__global__ void spmm1_gemm2_kernel(const float* __restrict__ b1, int N) {
    int warp = (blockIdx.x * blockDim.x + threadIdx.x) >> 5;
    int lane = threadIdx.x & 31;
    if (warp >= N) return;
    int beg = g_offs[warp], end = g_offs[warp + 1];
    const uint2* H0v = reinterpret_cast<const uint2*>(g_H0);
    float4 acc = make_float4(0.f, 0.f, 0.f, 0.f);
    int e = beg;
    for (; e + 1 < end; e += 2) {
        int2 p0 = g_epair[e], p1 = g_epair[e + 1];
        float w0 = __int_as_float(p0.y), w1 = __int_as_float(p1.y);
        uint2 v0 = H0v[(size_t)p0.x * 32 + lane];
        uint2 v1 = H0v[(size_t)p1.x * 32 + lane];
        fma_h4(acc, w0, v0);
        fma_h4(acc, w1, v1);
    }
    if (e < end) {
        int2 p0 = g_epair[e];
        uint2 v0 = H0v[(size_t)p0.x * 32 + lane];
        fma_h4(acc, __int_as_float(p0.y), v0);
    }
    float4 bb = __ldg(&reinterpret_cast<const float4*>(b1)[lane]);
    float4 h;
    h.x = fmaxf(acc.x + bb.x, 0.f);
    h.y = fmaxf(acc.y + bb.y, 0.f);
    h.z = fmaxf(acc.z + bb.z, 0.f);
    h.w = fmaxf(acc.w + bb.w, 0.f);

    const float4* W2t4 = reinterpret_cast<const float4*>(g_W2t);
    float p[16];
    #pragma unroll
    for (int c = 0; c < 16; c++) {
        float4 wv = __ldg(&W2t4[c * 32 + lane]);
        float t = h.x * wv.x;
        t = fmaf(h.y, wv.y, t);
        t = fmaf(h.z, wv.z, t);
        t = fmaf(h.w, wv.w, t);
        p[c] = t;
    }
    {   bool hi = (lane & 1);
        #pragma unroll
        for (int k = 0; k < 8; k++) {
            float send = hi ? p[k] : p[k + 8];
            float recv = __shfl_xor_sync(0xffffffffu, send, 1);
            p[k] = (hi ? p[k + 8] : p[k]) + recv;
        }
    }
    {   bool hi = (lane & 2);
        #pragma unroll
        for (int k = 0; k < 4; k++) {
            float send = hi ? p[k] : p[k + 4];
            float recv = __shfl_xor_sync(0xffffffffu, send, 2);
            p[k] = (hi ? p[k + 4] : p[k]) + recv;
        }
    }
    {   bool hi = (lane & 4);
        #pragma unroll
        for (int k = 0; k < 2; k++) {
            float send = hi ? p[k] : p[k + 2];
            float recv = __shfl_xor_sync(0xffffffffu, send, 4);
            p[k] = (hi ? p[k + 2] : p[k]) + recv;
        }
    }
    {   bool hi = (lane & 8);
        float send = hi ? p[0] : p[1];
        float recv = __shfl_xor_sync(0xffffffffu, send, 8);
        p[0] = (hi ? p[1] : p[0]) + recv;
    }
    p[0] += __shfl_xor_sync(0xffffffffu, p[0], 16);
    int c = ((lane & 1) << 3) | ((lane & 2) << 1) | ((lane & 4) >> 1) | ((lane & 8) >> 3);
    if (lane < 16) g_H2[(size_t)warp * NCLASS + c] = p[0];
}

// ---------------- SPMM2 + bias + log_softmax ----------------
__global__ void spmm2_kernel(const float* __restrict__ b2, float* __restrict__ out, int N) {
    int gwarp = (blockIdx.x * blockDim.x + threadIdx.x) >> 5;
    int lane = threadIdx.x & 31;
    int half = lane >> 4, l = lane & 15;
    int row = gwarp * 2 + half;
    float acc = 0.f;
    if (row < N) {
        int beg = g_offs[row], end = g_offs[row + 1];
        for (int e = beg; e < end; e++) {
            int2 pe = g_epair[e];
            float w = __int_as_float(pe.y);
            acc = fmaf(w, __ldg(&g_H2[(size_t)pe.x * NCLASS + l]), acc);
        }
    }
    acc += b2[l];
    float m = acc;
    #pragma unroll
    for (int o = 8; o > 0; o >>= 1) m = fmaxf(m, __shfl_xor_sync(0xffffffffu, m, o, 16));
    float ex = expf(acc - m);
    float s = ex;
    #pragma unroll
    for (int o = 8; o > 0; o >>= 1) s += __shfl_xor_sync(0xffffffffu, s, o, 16);
    if (row < N) out[(size_t)row * NCLASS + l] = acc - m - logf(s);
}

// ---------------- launch: fork/join — CSR build on side stream ∥ GEMM1 -------
extern "C" void kernel_launch(void* const* d_in, const int* in_sizes, int n_in,
                              void* d_out, int out_size) {
    const float* x   = (const float*)d_in[0];
    const float* W1  = (const float*)d_in[1];
    const float* b1  = (const float*)d_in[2];
    const float* W2  = (const float*)d_in[3];
    const float* b2  = (const float*)d_in[4];
    const float* ew  = (const float*)d_in[5];
    const int*   src = (const int*)d_in[6];
    const int*   dst = (const int*)d_in[7];
    float* out = (float*)d_out;

    const int N = in_sizes[0] / NFEAT;
    const int E = in_sizes[5];
    const int L = N + 1;
    const int NB = (L + 255) / 256;   // <= 512

    // one-time host-side resources (no device memory involved)
    static cudaStream_t s2 = nullptr;
    static cudaEvent_t ev_fork = nullptr, ev_join = nullptr;
    if (s2 == nullptr) {
        cudaStreamCreateWithFlags(&s2, cudaStreamNonBlocking);
        cudaEventCreateWithFlags(&ev_fork, cudaEventDisableTiming);
        cudaEventCreateWithFlags(&ev_join, cudaEventDisableTiming);
    }

    // common prep on main stream
    zero_prep_kernel<<<NB, 256>>>(W1, W2, L);

    // fork: CSR chain on s2, concurrent with gemm1 on main stream
    cudaEventRecord(ev_fork, 0);
    cudaStreamWaitEvent(s2, ev_fork, 0);

    degree_kernel<<<(E + 255) / 256, 256, 0, s2>>>(dst, E);
    scan_block_sums<<<NB, 256, 0, s2>>>(L);
    scan_partials<<<1, 512, 0, s2>>>(NB);
    scan_apply<<<NB, 256, 0, s2>>>(L);
    fill_csr<<<(E + 255) / 256, 256, 0, s2>>>(src, dst, ew, E);
    cudaEventRecord(ev_join, s2);

    gemm1_mma_kernel<<<(N + 127) / 128, 256>>>(x, N);   // main stream, ∥ CSR

    // join: spmm needs both CSR (s2) and H0 (main)
    cudaStreamWaitEvent(0, ev_join, 0);
    spmm1_gemm2_kernel<<<(N + 7) / 8, 256>>>(b1, N);
    spmm2_kernel<<<(N + 15) / 16, 256>>>(b2, out, N);
}